// round 1
// baseline (speedup 1.0000x reference)
#include <cuda_runtime.h>
#include <cuda_bf16.h>
#include <math.h>

// ---------------------------------------------------------------------------
// Problem constants (from reference setup_inputs): N=50000, E=600000,
// IN=128, HID=64, HEADS=4, OUT=10, G=64. Buffers sized with headroom.
// ---------------------------------------------------------------------------
#define MAXN 50048
#define MAXE 600064
#define MAXT (MAXE + MAXN)

// Scratch (device globals — no allocations allowed)
__device__ __align__(16) float g_hA[(size_t)MAXN * 256];   // GEMM output h
__device__ __align__(16) float g_agg[(size_t)MAXN * 256];  // aggregated messages
__device__ __align__(16) float g_hB[(size_t)MAXN * 256];   // layer activations
__device__ __align__(16) float g_e[(size_t)MAXT * 4];      // edge logits / exps
__device__ __align__(16) float g_m[(size_t)MAXN * 4];      // segment max
__device__ __align__(16) float g_den[(size_t)MAXN * 4];    // segment sum of exp
__device__ __align__(16) float g_als[(size_t)MAXN * 4];    // alpha_src coeffs
__device__ __align__(16) float g_ald[(size_t)MAXN * 4];    // alpha_dst coeffs
__device__ __align__(16) float g_pool[64 * 64];            // graph sums
__device__ __align__(16) float g_cnt[64];                  // graph counts

// ---------------------------------------------------------------------------
// Tiled SGEMM: C[M,N] = A[M,K] @ B[K,N]. BM=BN=64, BK=16, 256 thr, 4x4/thread.
// N divisible by 64, K divisible by 16 (holds for 128/256/64).
// ---------------------------------------------------------------------------
__global__ __launch_bounds__(256) void sgemm_kernel(
    const float* __restrict__ A, const float* __restrict__ B,
    float* __restrict__ C, int M, int N, int K)
{
    constexpr int BM = 64, BN = 64, BK = 16, TM = 4, TN = 4;
    __shared__ float As[BK][BM];
    __shared__ float Bs[BK][BN];

    int tid = threadIdx.x;
    int tx = tid % (BN / TN);   // 0..15
    int ty = tid / (BN / TN);   // 0..15
    int rowBase = blockIdx.y * BM;
    int colBase = blockIdx.x * BN;

    float acc[TM][TN];
#pragma unroll
    for (int i = 0; i < TM; i++)
#pragma unroll
        for (int j = 0; j < TN; j++) acc[i][j] = 0.f;

    int aRow = tid / (BK / 4);        // 0..63
    int aCol = (tid % (BK / 4)) * 4;  // 0,4,8,12
    int bRow = tid / (BN / 4);        // 0..15
    int bCol = (tid % (BN / 4)) * 4;  // 0..60

    for (int k0 = 0; k0 < K; k0 += BK) {
        float4 av = make_float4(0.f, 0.f, 0.f, 0.f);
        int gr = rowBase + aRow;
        if (gr < M)
            av = *(const float4*)(A + (size_t)gr * K + k0 + aCol);
        As[aCol + 0][aRow] = av.x;
        As[aCol + 1][aRow] = av.y;
        As[aCol + 2][aRow] = av.z;
        As[aCol + 3][aRow] = av.w;

        float4 bv = *(const float4*)(B + (size_t)(k0 + bRow) * N + colBase + bCol);
        *(float4*)&Bs[bRow][bCol] = bv;
        __syncthreads();

#pragma unroll
        for (int k = 0; k < BK; k++) {
            float ra[TM], rb[TN];
#pragma unroll
            for (int i = 0; i < TM; i++) ra[i] = As[k][ty * TM + i];
#pragma unroll
            for (int j = 0; j < TN; j++) rb[j] = Bs[k][tx * TN + j];
#pragma unroll
            for (int i = 0; i < TM; i++)
#pragma unroll
                for (int j = 0; j < TN; j++) acc[i][j] += ra[i] * rb[j];
        }
        __syncthreads();
    }

#pragma unroll
    for (int i = 0; i < TM; i++) {
        int r = rowBase + ty * TM + i;
        if (r >= M) continue;
        *(float4*)(C + (size_t)r * N + colBase + tx * TN) =
            make_float4(acc[i][0], acc[i][1], acc[i][2], acc[i][3]);
    }
}

// ---------------------------------------------------------------------------
// Attention coefficients: als[n,h] = <h[n,h,:], asrc[h,:]>, same for ald.
// ---------------------------------------------------------------------------
__global__ void attn_coef_kernel(const float* __restrict__ h,
                                 const float* __restrict__ asrc,
                                 const float* __restrict__ adst,
                                 float* __restrict__ als, float* __restrict__ ald,
                                 int N, int H, int C)
{
    int idx = blockIdx.x * blockDim.x + threadIdx.x;
    if (idx >= N * H) return;
    int n = idx / H, hd = idx % H;
    const float* hp = h + (size_t)n * H * C + hd * C;
    const float* a1 = asrc + hd * C;
    const float* a2 = adst + hd * C;
    float s1 = 0.f, s2 = 0.f;
    for (int c = 0; c < C; c += 4) {
        float4 hv = *(const float4*)(hp + c);
        float4 v1 = *(const float4*)(a1 + c);
        float4 v2 = *(const float4*)(a2 + c);
        s1 += hv.x * v1.x + hv.y * v1.y + hv.z * v1.z + hv.w * v1.w;
        s2 += hv.x * v2.x + hv.y * v2.y + hv.z * v2.z + hv.w * v2.w;
    }
    als[idx] = s1;
    ald[idx] = s2;
}

// ---------------------------------------------------------------------------
// Per-layer init: zero agg[N*HC]; m = -inf, den = 0 for N*H.
// ---------------------------------------------------------------------------
__global__ void init_layer_kernel(float* __restrict__ agg, float* __restrict__ m,
                                  float* __restrict__ den, int N, int H, int HC)
{
    int idx = blockIdx.x * blockDim.x + threadIdx.x;
    if (idx < N * HC) agg[idx] = 0.f;
    if (idx < N * H) {
        m[idx] = __int_as_float(0xFF800000);  // -inf
        den[idx] = 0.f;
    }
}

__device__ __forceinline__ void atomicMaxF(float* addr, float v)
{
    if (v >= 0.f) atomicMax((int*)addr, __float_as_int(v));
    else          atomicMin((unsigned int*)addr, __float_as_uint(v));
}

// ---------------------------------------------------------------------------
// Edge pass 1: e = leaky_relu(als[src]+ald[dst]); atomicMax per (dst,h).
// Edges e < E come from edge_index, e >= E are self-loops (src=dst=e-E).
// ---------------------------------------------------------------------------
__global__ void edge_logits_kernel(const int* __restrict__ ei, int E, int T, int H,
                                   const float* __restrict__ als,
                                   const float* __restrict__ ald,
                                   float* __restrict__ ebuf, float* __restrict__ m)
{
    int idx = blockIdx.x * blockDim.x + threadIdx.x;
    if (idx >= T * H) return;
    int e = idx / H, hd = idx % H;
    int s, d;
    if (e < E) { s = ei[e]; d = ei[E + e]; } else { s = d = e - E; }
    float v = als[s * H + hd] + ald[d * H + hd];
    v = (v > 0.f) ? v : 0.2f * v;
    ebuf[idx] = v;
    atomicMaxF(&m[d * H + hd], v);
}

// ---------------------------------------------------------------------------
// Edge pass 2: ex = exp(e - m[dst]); atomicAdd denominator.
// ---------------------------------------------------------------------------
__global__ void edge_exp_kernel(const int* __restrict__ ei, int E, int T, int H,
                                const float* __restrict__ m,
                                float* __restrict__ ebuf, float* __restrict__ den)
{
    int idx = blockIdx.x * blockDim.x + threadIdx.x;
    if (idx >= T * H) return;
    int e = idx / H, hd = idx % H;
    int d = (e < E) ? ei[E + e] : (e - E);
    float ex = __expf(ebuf[idx] - m[d * H + hd]);
    ebuf[idx] = ex;
    atomicAdd(&den[d * H + hd], ex);
}

// ---------------------------------------------------------------------------
// Edge pass 3: out[dst] += alpha * h[src]. HC/4 threads per edge, each doing
// one float4 with a vector reduction (red.global.add.v4.f32).
// ---------------------------------------------------------------------------
template <int H, int C>
__global__ __launch_bounds__(256) void edge_scatter_kernel(
    const int* __restrict__ ei, int E, int T,
    const float* __restrict__ h, const float* __restrict__ ebuf,
    const float* __restrict__ den, float* __restrict__ out)
{
    constexpr int HC = H * C;
    constexpr int TPE = HC / 4;              // threads per edge
    constexpr int EPB = 256 / TPE;           // edges per block
    int e = blockIdx.x * EPB + threadIdx.x / TPE;
    int t = threadIdx.x % TPE;               // float4 index within HC
    if (e >= T) return;
    int s, d;
    if (e < E) { s = ei[e]; d = ei[E + e]; } else { s = d = e - E; }
    int hd = (t * 4) / C;
    float alpha = ebuf[e * H + hd] / (den[d * H + hd] + 1e-16f);
    float4 v = *(const float4*)(h + (size_t)s * HC + t * 4);
    v.x *= alpha; v.y *= alpha; v.z *= alpha; v.w *= alpha;
    float* o = out + (size_t)d * HC + t * 4;
    asm volatile("red.global.add.v4.f32 [%0], {%1,%2,%3,%4};"
                 :: "l"(o), "f"(v.x), "f"(v.y), "f"(v.z), "f"(v.w)
                 : "memory");
}

// ---------------------------------------------------------------------------
// Finalize a layer: out = elu(agg + bias)
// ---------------------------------------------------------------------------
__global__ void bias_elu_kernel(const float* __restrict__ agg,
                                const float* __restrict__ b,
                                float* __restrict__ out, int N, int HC)
{
    int idx = blockIdx.x * blockDim.x + threadIdx.x;
    if (idx >= N * HC) return;
    float v = agg[idx] + b[idx % HC];
    out[idx] = (v > 0.f) ? v : expm1f(v);
}

// ---------------------------------------------------------------------------
// Pooling: accumulate per-graph sums and counts.
// ---------------------------------------------------------------------------
__global__ void pool_init_kernel()
{
    int idx = blockIdx.x * blockDim.x + threadIdx.x;
    if (idx < 64 * 64) g_pool[idx] = 0.f;
    if (idx < 64) g_cnt[idx] = 0.f;
}

__global__ void pool_acc_kernel(const float* __restrict__ h,
                                const int* __restrict__ batch, int N)
{
    int idx = blockIdx.x * blockDim.x + threadIdx.x;
    if (idx >= N * 64) return;
    int n = idx >> 6, c = idx & 63;
    int g = batch[n];
    atomicAdd(&g_pool[g * 64 + c], h[idx]);
    if (c == 0) atomicAdd(&g_cnt[g], 1.f);
}

// ---------------------------------------------------------------------------
// Final: out[g,o] = sum_k (pool[g,k]/max(cnt,1)) * linW[k,o] + linb[o]
// ---------------------------------------------------------------------------
__global__ void final_linear_kernel(const float* __restrict__ linW,
                                    const float* __restrict__ linb,
                                    float* __restrict__ out)
{
    int idx = blockIdx.x * blockDim.x + threadIdx.x;
    if (idx >= 64 * 10) return;
    int g = idx / 10, o = idx % 10;
    float inv = 1.f / fmaxf(g_cnt[g], 1.f);
    float s = 0.f;
    for (int k = 0; k < 64; k++)
        s += g_pool[g * 64 + k] * inv * linW[k * 10 + o];
    out[idx] = s + linb[o];
}

// ---------------------------------------------------------------------------
// Host orchestration (graph-capturable: kernel launches only)
// ---------------------------------------------------------------------------
static void run_layer(const float* in, int Kdim,
                      const float* W, const float* b,
                      const float* asrc, const float* adst,
                      int H, int C, int N, int E, int T,
                      const int* ei,
                      float* hA, float* agg, float* hOut,
                      float* ebuf, float* mbuf, float* den,
                      float* als, float* ald)
{
    int HC = H * C;
    // 1. h = in @ W
    {
        dim3 grid(HC / 64, (N + 63) / 64);
        sgemm_kernel<<<grid, 256>>>(in, W, hA, N, HC, Kdim);
    }
    // 2. attention coefficients
    attn_coef_kernel<<<(N * H + 255) / 256, 256>>>(hA, asrc, adst, als, ald, N, H, C);
    // 3. init m/den/agg
    init_layer_kernel<<<(N * HC + 255) / 256, 256>>>(agg, mbuf, den, N, H, HC);
    // 4. logits + segment max
    edge_logits_kernel<<<(T * H + 255) / 256, 256>>>(ei, E, T, H, als, ald, ebuf, mbuf);
    // 5. exp + segment sum
    edge_exp_kernel<<<(T * H + 255) / 256, 256>>>(ei, E, T, H, mbuf, ebuf, den);
    // 6. scatter messages
    if (H == 4) {
        constexpr int EPB = 256 / (256 / 4);   // 4 edges/block
        edge_scatter_kernel<4, 64><<<(T + EPB - 1) / EPB, 256>>>(ei, E, T, hA, ebuf, den, agg);
    } else {
        constexpr int EPB = 256 / (64 / 4);    // 16 edges/block
        edge_scatter_kernel<1, 64><<<(T + EPB - 1) / EPB, 256>>>(ei, E, T, hA, ebuf, den, agg);
    }
    // 7. bias + elu
    bias_elu_kernel<<<(N * HC + 255) / 256, 256>>>(agg, b, hOut, N, HC);
}

extern "C" void kernel_launch(void* const* d_in, const int* in_sizes, int n_in,
                              void* d_out, int out_size)
{
    const float* x     = (const float*)d_in[0];
    const int*   ei    = (const int*)d_in[1];
    const int*   batch = (const int*)d_in[2];
    const float* W1 = (const float*)d_in[3];   const float* b1 = (const float*)d_in[4];
    const float* as1 = (const float*)d_in[5];  const float* ad1 = (const float*)d_in[6];
    const float* W2 = (const float*)d_in[7];   const float* b2 = (const float*)d_in[8];
    const float* as2 = (const float*)d_in[9];  const float* ad2 = (const float*)d_in[10];
    const float* W3 = (const float*)d_in[11];  const float* b3 = (const float*)d_in[12];
    const float* as3 = (const float*)d_in[13]; const float* ad3 = (const float*)d_in[14];
    const float* linW = (const float*)d_in[15]; const float* linb = (const float*)d_in[16];
    float* out = (float*)d_out;

    int N = in_sizes[0] / 128;
    int E = in_sizes[1] / 2;
    int T = E + N;

    float *hA, *agg, *hB, *ebuf, *mbuf, *den, *als, *ald;
    cudaGetSymbolAddress((void**)&hA,  g_hA);
    cudaGetSymbolAddress((void**)&agg, g_agg);
    cudaGetSymbolAddress((void**)&hB,  g_hB);
    cudaGetSymbolAddress((void**)&ebuf, g_e);
    cudaGetSymbolAddress((void**)&mbuf, g_m);
    cudaGetSymbolAddress((void**)&den, g_den);
    cudaGetSymbolAddress((void**)&als, g_als);
    cudaGetSymbolAddress((void**)&ald, g_ald);

    // Layer 1: x[N,128] -> hB[N,256]
    run_layer(x, 128, W1, b1, as1, ad1, 4, 64, N, E, T, ei,
              hA, agg, hB, ebuf, mbuf, den, als, ald);
    // Layer 2: hB[N,256] -> hB[N,256]
    run_layer(hB, 256, W2, b2, as2, ad2, 4, 64, N, E, T, ei,
              hA, agg, hB, ebuf, mbuf, den, als, ald);
    // Layer 3: hB[N,256] -> hB[N,64]
    run_layer(hB, 256, W3, b3, as3, ad3, 1, 64, N, E, T, ei,
              hA, agg, hB, ebuf, mbuf, den, als, ald);

    // Pool + final linear
    pool_init_kernel<<<(64 * 64 + 255) / 256, 256>>>();
    pool_acc_kernel<<<(N * 64 + 255) / 256, 256>>>(hB, batch, N);
    final_linear_kernel<<<(640 + 255) / 256, 256>>>(linW, linb, out);
}

// round 2
// speedup vs baseline: 2.0345x; 2.0345x over previous
#include <cuda_runtime.h>
#include <cuda_bf16.h>
#include <math.h>

// ---------------------------------------------------------------------------
// Problem constants: N=50000, E=600000, IN=128, HID=64, HEADS=4, OUT=10, G=64
// ---------------------------------------------------------------------------
#define MAXN 50048
#define MAXE 600064

// Scratch (device globals — no allocations allowed)
__device__ __align__(16) float g_hA[(size_t)MAXN * 256];   // GEMM output h
__device__ __align__(16) float g_hB[(size_t)MAXN * 256];   // layer activations
__device__ __align__(16) float g_ex[(size_t)MAXE * 4];     // CSR-ordered exp(logit)
__device__ __align__(16) float g_als[(size_t)MAXN * 4];    // alpha_src coeffs
__device__ __align__(16) float g_ald[(size_t)MAXN * 4];    // alpha_dst coeffs
__device__ int g_deg[MAXN];
__device__ int g_rowptr[MAXN + 1];
__device__ int g_cursor[MAXN];
__device__ int g_col[MAXE];        // src per CSR slot
__device__ int g_dst[MAXE];        // dst per CSR slot
__device__ __align__(16) float g_pool[64 * 64];
__device__ __align__(16) float g_cnt[64];

// ---------------------------------------------------------------------------
// SGEMM: C[M,N] = A[M,K] @ B[K,N]. BM=128, BN=64, BK=16, 256 thr, 8x4/thread,
// double-buffered smem. N % 64 == 0, K % 16 == 0 (holds: 64/128/256).
// ---------------------------------------------------------------------------
__global__ __launch_bounds__(256) void sgemm_kernel(
    const float* __restrict__ A, const float* __restrict__ B,
    float* __restrict__ C, int M, int N, int K)
{
    constexpr int BM = 128, BN = 64, BK = 16;
    __shared__ float As[2][BK][BM];
    __shared__ float Bs[2][BK][BN];

    int tid = threadIdx.x;
    int rowBase = blockIdx.y * BM;
    int colBase = blockIdx.x * BN;

    // A loader: 2 float4 per thread. row = tid/4 + i*64, col4 = (tid%4)*4
    int aRow = tid >> 2;
    int aCol = (tid & 3) * 4;
    // B loader: 1 float4. bRow = tid/16, bCol = (tid%16)*4
    int bRow = tid >> 4;
    int bCol = (tid & 15) * 4;

    int ty = tid >> 4;   // 0..15 -> rows ty*8..+8
    int tx = tid & 15;   // 0..15 -> cols tx*4..+4

    float acc[8][4];
#pragma unroll
    for (int i = 0; i < 8; i++)
#pragma unroll
        for (int j = 0; j < 4; j++) acc[i][j] = 0.f;

    float4 pa0, pa1, pb;

    auto loadRegs = [&](int k0) {
        int r0 = rowBase + aRow;
        int r1 = rowBase + aRow + 64;
        pa0 = (r0 < M) ? *(const float4*)(A + (size_t)r0 * K + k0 + aCol)
                       : make_float4(0.f, 0.f, 0.f, 0.f);
        pa1 = (r1 < M) ? *(const float4*)(A + (size_t)r1 * K + k0 + aCol)
                       : make_float4(0.f, 0.f, 0.f, 0.f);
        pb = *(const float4*)(B + (size_t)(k0 + bRow) * N + colBase + bCol);
    };
    auto stSmem = [&](int buf) {
        As[buf][aCol + 0][aRow] = pa0.x;
        As[buf][aCol + 1][aRow] = pa0.y;
        As[buf][aCol + 2][aRow] = pa0.z;
        As[buf][aCol + 3][aRow] = pa0.w;
        As[buf][aCol + 0][aRow + 64] = pa1.x;
        As[buf][aCol + 1][aRow + 64] = pa1.y;
        As[buf][aCol + 2][aRow + 64] = pa1.z;
        As[buf][aCol + 3][aRow + 64] = pa1.w;
        *(float4*)&Bs[buf][bRow][bCol] = pb;
    };

    loadRegs(0);
    stSmem(0);
    __syncthreads();

    int buf = 0;
    for (int k0 = BK; k0 < K; k0 += BK) {
        loadRegs(k0);
#pragma unroll
        for (int k = 0; k < BK; k++) {
            float4 a0 = *(float4*)&As[buf][k][ty * 8];
            float4 a1 = *(float4*)&As[buf][k][ty * 8 + 4];
            float4 b0 = *(float4*)&Bs[buf][k][tx * 4];
            float ra[8] = {a0.x, a0.y, a0.z, a0.w, a1.x, a1.y, a1.z, a1.w};
            float rb[4] = {b0.x, b0.y, b0.z, b0.w};
#pragma unroll
            for (int i = 0; i < 8; i++)
#pragma unroll
                for (int j = 0; j < 4; j++) acc[i][j] += ra[i] * rb[j];
        }
        stSmem(buf ^ 1);
        __syncthreads();
        buf ^= 1;
    }
#pragma unroll
    for (int k = 0; k < BK; k++) {
        float4 a0 = *(float4*)&As[buf][k][ty * 8];
        float4 a1 = *(float4*)&As[buf][k][ty * 8 + 4];
        float4 b0 = *(float4*)&Bs[buf][k][tx * 4];
        float ra[8] = {a0.x, a0.y, a0.z, a0.w, a1.x, a1.y, a1.z, a1.w};
        float rb[4] = {b0.x, b0.y, b0.z, b0.w};
#pragma unroll
        for (int i = 0; i < 8; i++)
#pragma unroll
            for (int j = 0; j < 4; j++) acc[i][j] += ra[i] * rb[j];
    }

#pragma unroll
    for (int i = 0; i < 8; i++) {
        int r = rowBase + ty * 8 + i;
        if (r >= M) continue;
        *(float4*)(C + (size_t)r * N + colBase + tx * 4) =
            make_float4(acc[i][0], acc[i][1], acc[i][2], acc[i][3]);
    }
}

// ---------------------------------------------------------------------------
// CSR construction over the E real edges (self-loops handled inline later).
// ---------------------------------------------------------------------------
__global__ void csr_zero_kernel(int N)
{
    int i = blockIdx.x * blockDim.x + threadIdx.x;
    if (i < N) g_deg[i] = 0;
}

__global__ void csr_hist_kernel(const int* __restrict__ ei, int E)
{
    int e = blockIdx.x * blockDim.x + threadIdx.x;
    if (e < E) atomicAdd(&g_deg[ei[E + e]], 1);
}

// Single-block exclusive scan (warp shuffle + cross-warp), N up to MAXN.
__global__ __launch_bounds__(1024) void csr_scan_kernel(int N)
{
    __shared__ int wsum[32];
    __shared__ int carry;
    int tid = threadIdx.x;
    int lane = tid & 31, w = tid >> 5;
    if (tid == 0) { carry = 0; g_rowptr[0] = 0; }
    __syncthreads();
    for (int base = 0; base < N; base += 1024) {
        int i = base + tid;
        int v = (i < N) ? g_deg[i] : 0;
        int x = v;
#pragma unroll
        for (int off = 1; off < 32; off <<= 1) {
            int t = __shfl_up_sync(0xFFFFFFFF, x, off);
            if (lane >= off) x += t;
        }
        if (lane == 31) wsum[w] = x;
        __syncthreads();
        if (w == 0) {
            int s = wsum[lane];
#pragma unroll
            for (int off = 1; off < 32; off <<= 1) {
                int t = __shfl_up_sync(0xFFFFFFFF, s, off);
                if (lane >= off) s += t;
            }
            wsum[lane] = s;
        }
        __syncthreads();
        int incl = x + (w > 0 ? wsum[w - 1] : 0);
        int c = carry;
        if (i < N) {
            g_rowptr[i + 1] = c + incl;
            g_cursor[i] = c + incl - v;
        }
        __syncthreads();
        if (tid == 1023) carry = c + incl;
        __syncthreads();
    }
}

__global__ void csr_fill_kernel(const int* __restrict__ ei, int E)
{
    int e = blockIdx.x * blockDim.x + threadIdx.x;
    if (e >= E) return;
    int s = ei[e], d = ei[E + e];
    int p = atomicAdd(&g_cursor[d], 1);
    g_col[p] = s;
    g_dst[p] = d;
}

// ---------------------------------------------------------------------------
// Attention coefficients: als[n,h] = <h[n,h,:], asrc[h,:]>, same for ald.
// ---------------------------------------------------------------------------
__global__ void attn_coef_kernel(const float* __restrict__ h,
                                 const float* __restrict__ asrc,
                                 const float* __restrict__ adst,
                                 float* __restrict__ als, float* __restrict__ ald,
                                 int N, int H, int C)
{
    int idx = blockIdx.x * blockDim.x + threadIdx.x;
    if (idx >= N * H) return;
    int n = idx / H, hd = idx % H;
    const float* hp = h + (size_t)n * H * C + hd * C;
    const float* a1 = asrc + hd * C;
    const float* a2 = adst + hd * C;
    float s1 = 0.f, s2 = 0.f;
#pragma unroll 4
    for (int c = 0; c < C; c += 4) {
        float4 hv = *(const float4*)(hp + c);
        float4 v1 = *(const float4*)(a1 + c);
        float4 v2 = *(const float4*)(a2 + c);
        s1 += hv.x * v1.x + hv.y * v1.y + hv.z * v1.z + hv.w * v1.w;
        s2 += hv.x * v2.x + hv.y * v2.y + hv.z * v2.z + hv.w * v2.w;
    }
    als[idx] = s1;
    ald[idx] = s2;
}

// ---------------------------------------------------------------------------
// Edge exp: ex[p,h] = exp(leaky_relu(als[src]+ald[dst])) in CSR order.
// Softmax shift removed (shift-invariant; logits are O(10), exp safe in fp32).
// ---------------------------------------------------------------------------
__global__ void edge_ex4_kernel(int E, const float* __restrict__ als,
                                const float* __restrict__ ald)
{
    int p = blockIdx.x * blockDim.x + threadIdx.x;
    if (p >= E) return;
    int s = g_col[p], d = g_dst[p];
    float4 a = *(const float4*)&als[s * 4];
    float4 b = *(const float4*)&ald[d * 4];
    float4 v;
    v.x = a.x + b.x; v.x = (v.x > 0.f) ? v.x : 0.2f * v.x; v.x = __expf(v.x);
    v.y = a.y + b.y; v.y = (v.y > 0.f) ? v.y : 0.2f * v.y; v.y = __expf(v.y);
    v.z = a.z + b.z; v.z = (v.z > 0.f) ? v.z : 0.2f * v.z; v.z = __expf(v.z);
    v.w = a.w + b.w; v.w = (v.w > 0.f) ? v.w : 0.2f * v.w; v.w = __expf(v.w);
    *(float4*)&g_ex[(size_t)p * 4] = v;
}

__global__ void edge_ex1_kernel(int E, const float* __restrict__ als,
                                const float* __restrict__ ald)
{
    int p = blockIdx.x * blockDim.x + threadIdx.x;
    if (p >= E) return;
    float v = als[g_col[p]] + ald[g_dst[p]];
    v = (v > 0.f) ? v : 0.2f * v;
    g_ex[p] = __expf(v);
}

// ---------------------------------------------------------------------------
// Gather + softmax-normalize + bias + ELU, fused. One dst per TPE threads.
// ---------------------------------------------------------------------------
template <int H, int C>
__global__ __launch_bounds__(256) void gather_kernel(
    int N, const float* __restrict__ h,
    const float* __restrict__ als, const float* __restrict__ ald,
    const float* __restrict__ bias, float* __restrict__ out)
{
    constexpr int HC = H * C;
    constexpr int TPE = HC / 4;
    constexpr int DPB = 256 / TPE;
    int d = blockIdx.x * DPB + threadIdx.x / TPE;
    if (d >= N) return;
    int t = threadIdx.x % TPE;
    int hd = t / (C / 4);

    // self-loop
    float l = als[d * H + hd] + ald[d * H + hd];
    l = (l > 0.f) ? l : 0.2f * l;
    float exs = __expf(l);
    float4 hv = *(const float4*)(h + (size_t)d * HC + t * 4);
    float4 acc = make_float4(exs * hv.x, exs * hv.y, exs * hv.z, exs * hv.w);
    float den = exs;

    int p = g_rowptr[d], pend = g_rowptr[d + 1];
#pragma unroll 2
    for (; p < pend; p++) {
        int s = g_col[p];
        float ex = g_ex[(size_t)p * H + hd];
        float4 v = *(const float4*)(h + (size_t)s * HC + t * 4);
        acc.x += ex * v.x; acc.y += ex * v.y;
        acc.z += ex * v.z; acc.w += ex * v.w;
        den += ex;
    }
    float inv = 1.f / (den + 1e-16f);
    float4 bv = *(const float4*)(bias + t * 4);
    float4 o;
    o.x = acc.x * inv + bv.x; o.x = (o.x > 0.f) ? o.x : expm1f(o.x);
    o.y = acc.y * inv + bv.y; o.y = (o.y > 0.f) ? o.y : expm1f(o.y);
    o.z = acc.z * inv + bv.z; o.z = (o.z > 0.f) ? o.z : expm1f(o.z);
    o.w = acc.w * inv + bv.w; o.w = (o.w > 0.f) ? o.w : expm1f(o.w);
    *(float4*)(out + (size_t)d * HC + t * 4) = o;
}

// ---------------------------------------------------------------------------
// Pooling (batch is sorted): run-length local accumulate, rare atomic flush.
// ---------------------------------------------------------------------------
__global__ void pool_init_kernel()
{
    int idx = blockIdx.x * blockDim.x + threadIdx.x;
    if (idx < 64 * 64) g_pool[idx] = 0.f;
    if (idx < 64) g_cnt[idx] = 0.f;
}

__global__ __launch_bounds__(256) void pool_acc_kernel(
    const float* __restrict__ h, const int* __restrict__ batch, int N)
{
    int c = threadIdx.x & 63;
    int lane = threadIdx.x >> 6;
    int n0 = blockIdx.x * 64 + lane * 16;
    float acc = 0.f;
    int curg = -1, cnt = 0;
    for (int k = 0; k < 16; k++) {
        int n = n0 + k;
        if (n >= N) break;
        int g = batch[n];
        if (g != curg) {
            if (curg >= 0) {
                atomicAdd(&g_pool[curg * 64 + c], acc);
                if (c == 0) atomicAdd(&g_cnt[curg], (float)cnt);
            }
            curg = g; acc = 0.f; cnt = 0;
        }
        acc += h[(size_t)n * 64 + c];
        cnt++;
    }
    if (curg >= 0) {
        atomicAdd(&g_pool[curg * 64 + c], acc);
        if (c == 0) atomicAdd(&g_cnt[curg], (float)cnt);
    }
}

__global__ void final_linear_kernel(const float* __restrict__ linW,
                                    const float* __restrict__ linb,
                                    float* __restrict__ out)
{
    int idx = blockIdx.x * blockDim.x + threadIdx.x;
    if (idx >= 64 * 10) return;
    int g = idx / 10, o = idx % 10;
    float inv = 1.f / fmaxf(g_cnt[g], 1.f);
    float s = 0.f;
#pragma unroll 8
    for (int k = 0; k < 64; k++)
        s += g_pool[g * 64 + k] * inv * linW[k * 10 + o];
    out[idx] = s + linb[o];
}

// ---------------------------------------------------------------------------
// Host orchestration (graph-capturable: kernel launches only)
// ---------------------------------------------------------------------------
static void run_layer(const float* in, int Kdim,
                      const float* W, const float* b,
                      const float* asrc, const float* adst,
                      int H, int C, int N, int E,
                      float* hA, float* hOut, float* als, float* ald)
{
    int HC = H * C;
    {
        dim3 grid(HC / 64, (N + 127) / 128);
        sgemm_kernel<<<grid, 256>>>(in, W, hA, N, HC, Kdim);
    }
    attn_coef_kernel<<<(N * H + 255) / 256, 256>>>(hA, asrc, adst, als, ald, N, H, C);
    if (H == 4) {
        edge_ex4_kernel<<<(E + 255) / 256, 256>>>(E, als, ald);
        gather_kernel<4, 64><<<(N + 3) / 4, 256>>>(N, hA, als, ald, b, hOut);
    } else {
        edge_ex1_kernel<<<(E + 255) / 256, 256>>>(E, als, ald);
        gather_kernel<1, 64><<<(N + 15) / 16, 256>>>(N, hA, als, ald, b, hOut);
    }
}

extern "C" void kernel_launch(void* const* d_in, const int* in_sizes, int n_in,
                              void* d_out, int out_size)
{
    const float* x     = (const float*)d_in[0];
    const int*   ei    = (const int*)d_in[1];
    const int*   batch = (const int*)d_in[2];
    const float* W1 = (const float*)d_in[3];   const float* b1 = (const float*)d_in[4];
    const float* as1 = (const float*)d_in[5];  const float* ad1 = (const float*)d_in[6];
    const float* W2 = (const float*)d_in[7];   const float* b2 = (const float*)d_in[8];
    const float* as2 = (const float*)d_in[9];  const float* ad2 = (const float*)d_in[10];
    const float* W3 = (const float*)d_in[11];  const float* b3 = (const float*)d_in[12];
    const float* as3 = (const float*)d_in[13]; const float* ad3 = (const float*)d_in[14];
    const float* linW = (const float*)d_in[15]; const float* linb = (const float*)d_in[16];
    float* out = (float*)d_out;

    int N = in_sizes[0] / 128;
    int E = in_sizes[1] / 2;

    float *hA, *hB, *als, *ald;
    cudaGetSymbolAddress((void**)&hA,  g_hA);
    cudaGetSymbolAddress((void**)&hB,  g_hB);
    cudaGetSymbolAddress((void**)&als, g_als);
    cudaGetSymbolAddress((void**)&ald, g_ald);

    // CSR build (once; edges identical across layers)
    csr_zero_kernel<<<(N + 255) / 256, 256>>>(N);
    csr_hist_kernel<<<(E + 255) / 256, 256>>>(ei, E);
    csr_scan_kernel<<<1, 1024>>>(N);
    csr_fill_kernel<<<(E + 255) / 256, 256>>>(ei, E);

    // Layer 1: x[N,128] -> hB[N,256]
    run_layer(x, 128, W1, b1, as1, ad1, 4, 64, N, E, hA, hB, als, ald);
    // Layer 2: hB[N,256] -> hB[N,256]
    run_layer(hB, 256, W2, b2, as2, ad2, 4, 64, N, E, hA, hB, als, ald);
    // Layer 3: hB[N,256] -> hB[N,64]  (gather reads hA, writes hB)
    run_layer(hB, 256, W3, b3, as3, ad3, 1, 64, N, E, hA, hB, als, ald);

    // Pool + final linear
    pool_init_kernel<<<(64 * 64 + 255) / 256, 256>>>();
    pool_acc_kernel<<<(N + 63) / 64, 256>>>(hB, batch, N);
    final_linear_kernel<<<3, 256>>>(linW, linb, out);
}

// round 4
// speedup vs baseline: 2.1068x; 1.0355x over previous
#include <cuda_runtime.h>
#include <math.h>
#include <stdint.h>

// ---------------------------------------------------------------------------
// Problem constants: N=50000, E=600000, IN=128, HID=64, HEADS=4, OUT=10, G=64
// ---------------------------------------------------------------------------
#define MAXN 50048
#define MAXE 600064

// Scratch (device globals — no allocations allowed)
__device__ __align__(16) float g_hA[(size_t)MAXN * 256];   // GEMM output h
__device__ __align__(16) float g_hB[(size_t)MAXN * 256];   // layer activations
__device__ __align__(16) float g_ex[(size_t)MAXE * 4];     // CSR-ordered exp(logit)
__device__ __align__(16) float g_als[(size_t)MAXN * 4];    // alpha_src coeffs
__device__ __align__(16) float g_ald[(size_t)MAXN * 4];    // alpha_dst coeffs
__device__ int g_deg[MAXN];
__device__ int g_rowptr[MAXN + 1];
__device__ int g_cursor[MAXN];
__device__ int g_col[MAXE];        // src per CSR slot
__device__ int g_dst[MAXE];        // dst per CSR slot
__device__ __align__(16) float g_pool[64 * 64];
__device__ __align__(16) float g_cnt[64];

// ---------------------------------------------------------------------------
// TF32 tensor-core GEMM: C[M,N] = A[M,K] @ B[K,N], fp32 in/out, tf32 mma.
// BM=128, BN=64, BK=32. 8 warps; warp tile 32x32 (2 m16-frags x 4 n8-frags).
// Shared memory holds A/B in FRAGMENT order so consumers do LDS.128/LDS.64.
// Requires: N % 64 == 0, K % 32 == 0 (holds: 64/128/256).
// ---------------------------------------------------------------------------
__device__ __forceinline__ uint32_t f2tf32(float x)
{
    uint32_t r;
    asm("cvt.rna.tf32.f32 %0, %1;" : "=r"(r) : "f"(x));
    return r;
}

__global__ __launch_bounds__(256) void tf32_gemm_kernel(
    const float* __restrict__ A, const float* __restrict__ B,
    float* __restrict__ C, int M, int N, int K)
{
    // As frag layout: [kstep 0..3][m16 0..7] { [lane 0..31][reg 0..3] }  (16 KB)
    // Bs frag layout: [kstep 0..3][n8 0..7]  { [lane 0..31][reg 0..1] }  (8 KB)
    __shared__ uint32_t As[2][4096];
    __shared__ uint32_t Bs[2][2048];

    int tid = threadIdx.x;
    int warp = tid >> 5, lane = tid & 31;
    int gid = lane >> 2, tig = lane & 3;
    int wm = warp & 3, wn = warp >> 2;           // wm 0..3 (M), wn 0..1 (N)
    int rowBase = blockIdx.y * 128;
    int colBase = blockIdx.x * 64;

    float acc[2][4][4];
#pragma unroll
    for (int i = 0; i < 2; i++)
#pragma unroll
        for (int j = 0; j < 4; j++)
#pragma unroll
            for (int r = 0; r < 4; r++) acc[i][j][r] = 0.f;

    // ---- loader indexing ----
    // A tile: 128 rows x 32 k = 1024 float4 (4 per thread, along k)
    //   f4 index f = tid + i*256 : m = f>>3, k = (f&7)*4
    // B tile: 32 k-rows x 64 n = 512 float4 (2 per thread, along n)
    //   f4 index f = tid + i*256 : k = f>>4, n = (f&15)*4
    float4 ra[4], rb[2];

    auto loadRegs = [&](int k0) {
#pragma unroll
        for (int i = 0; i < 4; i++) {
            int f = tid + i * 256;
            int m = f >> 3, k = (f & 7) * 4;
            int gr = rowBase + m;
            ra[i] = (gr < M) ? *(const float4*)(A + (size_t)gr * K + k0 + k)
                             : make_float4(0.f, 0.f, 0.f, 0.f);
        }
#pragma unroll
        for (int i = 0; i < 2; i++) {
            int f = tid + i * 256;
            int k = f >> 4, n = (f & 15) * 4;
            rb[i] = *(const float4*)(B + (size_t)(k0 + k) * N + colBase + n);
        }
    };

    auto stSmem = [&](int buf) {
#pragma unroll
        for (int i = 0; i < 4; i++) {
            int f = tid + i * 256;
            int m = f >> 3, kb = (f & 7) * 4;     // kb in {0,4,...,28}
            int kstep = kb >> 3;
            int kh = (kb & 7) >> 2;               // 0 or 1 (same for all 4 elems)
            int m16 = m >> 4, r = m & 15;
            int agid = r & 7, hi = r >> 3;
            int reg = kh * 2 + hi;
            // slot = ((kstep*8+m16)*32 + lane)*4 + reg; lane = agid*4 + tig,
            // the 4 elements are tig=0..3 -> slot step = +4.
            uint32_t base = ((kstep * 8 + m16) * 32 + agid * 4) * 4 + reg;
            As[buf][base +  0] = f2tf32(ra[i].x);
            As[buf][base +  4] = f2tf32(ra[i].y);
            As[buf][base +  8] = f2tf32(ra[i].z);
            As[buf][base + 12] = f2tf32(ra[i].w);
        }
#pragma unroll
        for (int i = 0; i < 2; i++) {
            int f = tid + i * 256;
            int k = f >> 4, nb = (f & 15) * 4;
            int kstep = k >> 3;
            int kk = k & 7;
            int btig = kk & 3, half = kk >> 2;
            int n8 = nb >> 3;
            int bgid0 = nb & 7;                   // 0 or 4; gid = bgid0..bgid0+3
            // slot = ((kstep*8+n8)*32 + lane)*2 + half; lane = gid*4 + btig,
            // the 4 elements are gid=bgid0..bgid0+3 -> slot step = +8.
            uint32_t base = ((kstep * 8 + n8) * 32 + bgid0 * 4 + btig) * 2 + half;
            Bs[buf][base +  0] = f2tf32(rb[i].x);
            Bs[buf][base +  8] = f2tf32(rb[i].y);
            Bs[buf][base + 16] = f2tf32(rb[i].z);
            Bs[buf][base + 24] = f2tf32(rb[i].w);
        }
    };

    auto compute = [&](int buf) {
#pragma unroll
        for (int ks = 0; ks < 4; ks++) {
            uint32_t a[2][4];
            uint32_t b[4][2];
#pragma unroll
            for (int mf = 0; mf < 2; mf++) {
                uint32_t off = ((ks * 8 + wm * 2 + mf) * 32 + lane) * 4;
                uint4 v = *(const uint4*)&As[buf][off];
                a[mf][0] = v.x; a[mf][1] = v.y; a[mf][2] = v.z; a[mf][3] = v.w;
            }
#pragma unroll
            for (int nf = 0; nf < 4; nf++) {
                uint32_t off = ((ks * 8 + wn * 4 + nf) * 32 + lane) * 2;
                uint2 v = *(const uint2*)&Bs[buf][off];
                b[nf][0] = v.x; b[nf][1] = v.y;
            }
#pragma unroll
            for (int mf = 0; mf < 2; mf++)
#pragma unroll
                for (int nf = 0; nf < 4; nf++) {
                    asm volatile(
                        "mma.sync.aligned.m16n8k8.row.col.f32.tf32.tf32.f32 "
                        "{%0,%1,%2,%3},{%4,%5,%6,%7},{%8,%9},{%0,%1,%2,%3};"
                        : "+f"(acc[mf][nf][0]), "+f"(acc[mf][nf][1]),
                          "+f"(acc[mf][nf][2]), "+f"(acc[mf][nf][3])
                        : "r"(a[mf][0]), "r"(a[mf][1]), "r"(a[mf][2]), "r"(a[mf][3]),
                          "r"(b[nf][0]), "r"(b[nf][1]));
                }
        }
    };

    loadRegs(0);
    stSmem(0);
    __syncthreads();

    int buf = 0;
    for (int k0 = 32; k0 < K; k0 += 32) {
        loadRegs(k0);
        compute(buf);
        stSmem(buf ^ 1);
        __syncthreads();
        buf ^= 1;
    }
    compute(buf);

    // Epilogue: c0/c1 contiguous (col tig*2, tig*2+1); c2/c3 at row+8.
#pragma unroll
    for (int mf = 0; mf < 2; mf++) {
        int row0 = rowBase + (wm * 2 + mf) * 16 + gid;
#pragma unroll
        for (int nf = 0; nf < 4; nf++) {
            int col = colBase + (wn * 4 + nf) * 8 + tig * 2;
            if (row0 < M)
                *(float2*)(C + (size_t)row0 * N + col) =
                    make_float2(acc[mf][nf][0], acc[mf][nf][1]);
            if (row0 + 8 < M)
                *(float2*)(C + (size_t)(row0 + 8) * N + col) =
                    make_float2(acc[mf][nf][2], acc[mf][nf][3]);
        }
    }
}

// ---------------------------------------------------------------------------
// CSR construction over the E real edges (self-loops handled inline later).
// ---------------------------------------------------------------------------
__global__ void csr_zero_kernel(int N)
{
    int i = blockIdx.x * blockDim.x + threadIdx.x;
    if (i < N) g_deg[i] = 0;
}

__global__ void csr_hist_kernel(const int* __restrict__ ei, int E)
{
    int e = blockIdx.x * blockDim.x + threadIdx.x;
    if (e < E) atomicAdd(&g_deg[ei[E + e]], 1);
}

// Single-block exclusive scan (warp shuffle + cross-warp), N up to MAXN.
__global__ __launch_bounds__(1024) void csr_scan_kernel(int N)
{
    __shared__ int wsum[32];
    __shared__ int carry;
    int tid = threadIdx.x;
    int lane = tid & 31, w = tid >> 5;
    if (tid == 0) { carry = 0; g_rowptr[0] = 0; }
    __syncthreads();
    for (int base = 0; base < N; base += 1024) {
        int i = base + tid;
        int v = (i < N) ? g_deg[i] : 0;
        int x = v;
#pragma unroll
        for (int off = 1; off < 32; off <<= 1) {
            int t = __shfl_up_sync(0xFFFFFFFF, x, off);
            if (lane >= off) x += t;
        }
        if (lane == 31) wsum[w] = x;
        __syncthreads();
        if (w == 0) {
            int s = wsum[lane];
#pragma unroll
            for (int off = 1; off < 32; off <<= 1) {
                int t = __shfl_up_sync(0xFFFFFFFF, s, off);
                if (lane >= off) s += t;
            }
            wsum[lane] = s;
        }
        __syncthreads();
        int incl = x + (w > 0 ? wsum[w - 1] : 0);
        int c = carry;
        if (i < N) {
            g_rowptr[i + 1] = c + incl;
            g_cursor[i] = c + incl - v;
        }
        __syncthreads();
        if (tid == 1023) carry = c + incl;
        __syncthreads();
    }
}

__global__ void csr_fill_kernel(const int* __restrict__ ei, int E)
{
    int e = blockIdx.x * blockDim.x + threadIdx.x;
    if (e >= E) return;
    int s = ei[e], d = ei[E + e];
    int p = atomicAdd(&g_cursor[d], 1);
    g_col[p] = s;
    g_dst[p] = d;
}

// ---------------------------------------------------------------------------
// Attention coefficients: als[n,h] = <h[n,h,:], asrc[h,:]>, same for ald.
// ---------------------------------------------------------------------------
__global__ void attn_coef_kernel(const float* __restrict__ h,
                                 const float* __restrict__ asrc,
                                 const float* __restrict__ adst,
                                 float* __restrict__ als, float* __restrict__ ald,
                                 int N, int H, int C)
{
    int idx = blockIdx.x * blockDim.x + threadIdx.x;
    if (idx >= N * H) return;
    int n = idx / H, hd = idx % H;
    const float* hp = h + (size_t)n * H * C + hd * C;
    const float* a1 = asrc + hd * C;
    const float* a2 = adst + hd * C;
    float s1 = 0.f, s2 = 0.f;
#pragma unroll 4
    for (int c = 0; c < C; c += 4) {
        float4 hv = *(const float4*)(hp + c);
        float4 v1 = *(const float4*)(a1 + c);
        float4 v2 = *(const float4*)(a2 + c);
        s1 += hv.x * v1.x + hv.y * v1.y + hv.z * v1.z + hv.w * v1.w;
        s2 += hv.x * v2.x + hv.y * v2.y + hv.z * v2.z + hv.w * v2.w;
    }
    als[idx] = s1;
    ald[idx] = s2;
}

// ---------------------------------------------------------------------------
// Edge exp: ex[p,h] = exp(leaky_relu(als[src]+ald[dst])) in CSR order.
// ---------------------------------------------------------------------------
__global__ void edge_ex4_kernel(int E, const float* __restrict__ als,
                                const float* __restrict__ ald)
{
    int p = blockIdx.x * blockDim.x + threadIdx.x;
    if (p >= E) return;
    int s = g_col[p], d = g_dst[p];
    float4 a = *(const float4*)&als[s * 4];
    float4 b = *(const float4*)&ald[d * 4];
    float4 v;
    v.x = a.x + b.x; v.x = (v.x > 0.f) ? v.x : 0.2f * v.x; v.x = __expf(v.x);
    v.y = a.y + b.y; v.y = (v.y > 0.f) ? v.y : 0.2f * v.y; v.y = __expf(v.y);
    v.z = a.z + b.z; v.z = (v.z > 0.f) ? v.z : 0.2f * v.z; v.z = __expf(v.z);
    v.w = a.w + b.w; v.w = (v.w > 0.f) ? v.w : 0.2f * v.w; v.w = __expf(v.w);
    *(float4*)&g_ex[(size_t)p * 4] = v;
}

__global__ void edge_ex1_kernel(int E, const float* __restrict__ als,
                                const float* __restrict__ ald)
{
    int p = blockIdx.x * blockDim.x + threadIdx.x;
    if (p >= E) return;
    float v = als[g_col[p]] + ald[g_dst[p]];
    v = (v > 0.f) ? v : 0.2f * v;
    g_ex[p] = __expf(v);
}

// ---------------------------------------------------------------------------
// Gather + softmax-normalize + bias + ELU, fused. One dst per TPE threads.
// ---------------------------------------------------------------------------
template <int H, int C>
__global__ __launch_bounds__(256) void gather_kernel(
    int N, const float* __restrict__ h,
    const float* __restrict__ als, const float* __restrict__ ald,
    const float* __restrict__ bias, float* __restrict__ out)
{
    constexpr int HC = H * C;
    constexpr int TPE = HC / 4;
    constexpr int DPB = 256 / TPE;
    int d = blockIdx.x * DPB + threadIdx.x / TPE;
    if (d >= N) return;
    int t = threadIdx.x % TPE;
    int hd = t / (C / 4);

    // self-loop
    float l = als[d * H + hd] + ald[d * H + hd];
    l = (l > 0.f) ? l : 0.2f * l;
    float exs = __expf(l);
    float4 hv = *(const float4*)(h + (size_t)d * HC + t * 4);
    float4 acc = make_float4(exs * hv.x, exs * hv.y, exs * hv.z, exs * hv.w);
    float den = exs;

    int p = g_rowptr[d], pend = g_rowptr[d + 1];
#pragma unroll 2
    for (; p < pend; p++) {
        int s = g_col[p];
        float ex = g_ex[(size_t)p * H + hd];
        float4 v = *(const float4*)(h + (size_t)s * HC + t * 4);
        acc.x += ex * v.x; acc.y += ex * v.y;
        acc.z += ex * v.z; acc.w += ex * v.w;
        den += ex;
    }
    float inv = 1.f / (den + 1e-16f);
    float4 bv = *(const float4*)(bias + t * 4);
    float4 o;
    o.x = acc.x * inv + bv.x; o.x = (o.x > 0.f) ? o.x : expm1f(o.x);
    o.y = acc.y * inv + bv.y; o.y = (o.y > 0.f) ? o.y : expm1f(o.y);
    o.z = acc.z * inv + bv.z; o.z = (o.z > 0.f) ? o.z : expm1f(o.z);
    o.w = acc.w * inv + bv.w; o.w = (o.w > 0.f) ? o.w : expm1f(o.w);
    *(float4*)(out + (size_t)d * HC + t * 4) = o;
}

// ---------------------------------------------------------------------------
// Pooling (batch is sorted): run-length local accumulate, rare atomic flush.
// ---------------------------------------------------------------------------
__global__ void pool_init_kernel()
{
    int idx = blockIdx.x * blockDim.x + threadIdx.x;
    if (idx < 64 * 64) g_pool[idx] = 0.f;
    if (idx < 64) g_cnt[idx] = 0.f;
}

__global__ __launch_bounds__(256) void pool_acc_kernel(
    const float* __restrict__ h, const int* __restrict__ batch, int N)
{
    int c = threadIdx.x & 63;
    int lane = threadIdx.x >> 6;
    int n0 = blockIdx.x * 64 + lane * 16;
    float acc = 0.f;
    int curg = -1, cnt = 0;
    for (int k = 0; k < 16; k++) {
        int n = n0 + k;
        if (n >= N) break;
        int g = batch[n];
        if (g != curg) {
            if (curg >= 0) {
                atomicAdd(&g_pool[curg * 64 + c], acc);
                if (c == 0) atomicAdd(&g_cnt[curg], (float)cnt);
            }
            curg = g; acc = 0.f; cnt = 0;
        }
        acc += h[(size_t)n * 64 + c];
        cnt++;
    }
    if (curg >= 0) {
        atomicAdd(&g_pool[curg * 64 + c], acc);
        if (c == 0) atomicAdd(&g_cnt[curg], (float)cnt);
    }
}

__global__ void final_linear_kernel(const float* __restrict__ linW,
                                    const float* __restrict__ linb,
                                    float* __restrict__ out)
{
    int idx = blockIdx.x * blockDim.x + threadIdx.x;
    if (idx >= 64 * 10) return;
    int g = idx / 10, o = idx % 10;
    float inv = 1.f / fmaxf(g_cnt[g], 1.f);
    float s = 0.f;
#pragma unroll 8
    for (int k = 0; k < 64; k++)
        s += g_pool[g * 64 + k] * inv * linW[k * 10 + o];
    out[idx] = s + linb[o];
}

// ---------------------------------------------------------------------------
// Host orchestration (graph-capturable: kernel launches only)
// ---------------------------------------------------------------------------
static void run_layer(const float* in, int Kdim,
                      const float* W, const float* b,
                      const float* asrc, const float* adst,
                      int H, int C, int N, int E,
                      float* hA, float* hOut, float* als, float* ald)
{
    int HC = H * C;
    {
        dim3 grid(HC / 64, (N + 127) / 128);
        tf32_gemm_kernel<<<grid, 256>>>(in, W, hA, N, HC, Kdim);
    }
    attn_coef_kernel<<<(N * H + 255) / 256, 256>>>(hA, asrc, adst, als, ald, N, H, C);
    if (H == 4) {
        edge_ex4_kernel<<<(E + 255) / 256, 256>>>(E, als, ald);
        gather_kernel<4, 64><<<(N + 3) / 4, 256>>>(N, hA, als, ald, b, hOut);
    } else {
        edge_ex1_kernel<<<(E + 255) / 256, 256>>>(E, als, ald);
        gather_kernel<1, 64><<<(N + 15) / 16, 256>>>(N, hA, als, ald, b, hOut);
    }
}

extern "C" void kernel_launch(void* const* d_in, const int* in_sizes, int n_in,
                              void* d_out, int out_size)
{
    const float* x     = (const float*)d_in[0];
    const int*   ei    = (const int*)d_in[1];
    const int*   batch = (const int*)d_in[2];
    const float* W1 = (const float*)d_in[3];   const float* b1 = (const float*)d_in[4];
    const float* as1 = (const float*)d_in[5];  const float* ad1 = (const float*)d_in[6];
    const float* W2 = (const float*)d_in[7];   const float* b2 = (const float*)d_in[8];
    const float* as2 = (const float*)d_in[9];  const float* ad2 = (const float*)d_in[10];
    const float* W3 = (const float*)d_in[11];  const float* b3 = (const float*)d_in[12];
    const float* as3 = (const float*)d_in[13]; const float* ad3 = (const float*)d_in[14];
    const float* linW = (const float*)d_in[15]; const float* linb = (const float*)d_in[16];
    float* out = (float*)d_out;

    int N = in_sizes[0] / 128;
    int E = in_sizes[1] / 2;

    float *hA, *hB, *als, *ald;
    cudaGetSymbolAddress((void**)&hA,  g_hA);
    cudaGetSymbolAddress((void**)&hB,  g_hB);
    cudaGetSymbolAddress((void**)&als, g_als);
    cudaGetSymbolAddress((void**)&ald, g_ald);

    // CSR build (once; edges identical across layers)
    csr_zero_kernel<<<(N + 255) / 256, 256>>>(N);
    csr_hist_kernel<<<(E + 255) / 256, 256>>>(ei, E);
    csr_scan_kernel<<<1, 1024>>>(N);
    csr_fill_kernel<<<(E + 255) / 256, 256>>>(ei, E);

    // Layer 1: x[N,128] -> hB[N,256]
    run_layer(x, 128, W1, b1, as1, ad1, 4, 64, N, E, hA, hB, als, ald);
    // Layer 2: hB[N,256] -> hB[N,256]
    run_layer(hB, 256, W2, b2, as2, ad2, 4, 64, N, E, hA, hB, als, ald);
    // Layer 3: hB[N,256] -> hB[N,64]
    run_layer(hB, 256, W3, b3, as3, ad3, 1, 64, N, E, hA, hB, als, ald);

    // Pool + final linear
    pool_init_kernel<<<(64 * 64 + 255) / 256, 256>>>();
    pool_acc_kernel<<<(N + 63) / 64, 256>>>(hB, batch, N);
    final_linear_kernel<<<3, 256>>>(linW, linb, out);
}

// round 5
// speedup vs baseline: 2.1970x; 1.0428x over previous
#include <cuda_runtime.h>
#include <math.h>
#include <stdint.h>

// ---------------------------------------------------------------------------
// Problem constants: N=50000, E=600000, IN=128, HID=64, HEADS=4, OUT=10, G=64
// ---------------------------------------------------------------------------
#define MAXN 50048
#define MAXE 600064

// Scratch (device globals — no allocations allowed)
__device__ __align__(16) float g_hA[(size_t)MAXN * 256];   // GEMM output h
__device__ __align__(16) float g_hB[(size_t)MAXN * 256];   // layer activations
__device__ __align__(16) float g_ex[(size_t)MAXE * 4];     // CSR-ordered exp(logit)
__device__ __align__(16) float g_als[(size_t)MAXN * 4];    // alpha_src coeffs
__device__ __align__(16) float g_ald[(size_t)MAXN * 4];    // alpha_dst coeffs
__device__ int g_deg[MAXN];
__device__ int g_rowptr[MAXN + 1];
__device__ int g_cursor[MAXN];
__device__ int g_col[MAXE];        // src per CSR slot
__device__ int g_dst[MAXE];        // dst per CSR slot
__device__ __align__(16) float g_pool[64 * 64];
__device__ __align__(16) float g_cnt[64];

// ---------------------------------------------------------------------------
// TF32 tensor-core GEMM: C[M,N] = A[M,K] @ B[K,N], fp32 in/out, tf32 mma.
// BM=128, BN=64, BK=32. 8 warps; warp tile 32x32 (2 m16-frags x 4 n8-frags).
// Smem: natural row-major tiles with XOR swizzle -> conflict-free STS.128
// stores AND conflict-free scalar LDS fragment reads.
//   As[m][k ^ ((m&7)*4)]  (128 x 32 words)
//   Bs[k][n ^ ((k&3)*8)]  (32 x 64 words)
// Requires: N % 64 == 0, K % 32 == 0 (holds: 64/128/256).
// ---------------------------------------------------------------------------
__device__ __forceinline__ uint32_t f2tf32(float x)
{
    uint32_t r;
    asm("cvt.rna.tf32.f32 %0, %1;" : "=r"(r) : "f"(x));
    return r;
}

__global__ __launch_bounds__(256) void tf32_gemm_kernel(
    const float* __restrict__ A, const float* __restrict__ B,
    float* __restrict__ C, int M, int N, int K)
{
    __shared__ uint32_t As[2][4096];   // 128 x 32, swizzled
    __shared__ uint32_t Bs[2][2048];   // 32 x 64, swizzled

    int tid = threadIdx.x;
    int warp = tid >> 5, lane = tid & 31;
    int gid = lane >> 2, tig = lane & 3;
    int wm = warp & 3, wn = warp >> 2;           // wm 0..3 (M), wn 0..1 (N)
    int rowBase = blockIdx.y * 128;
    int colBase = blockIdx.x * 64;

    float acc[2][4][4];
#pragma unroll
    for (int i = 0; i < 2; i++)
#pragma unroll
        for (int j = 0; j < 4; j++)
#pragma unroll
            for (int r = 0; r < 4; r++) acc[i][j][r] = 0.f;

    // A tile: 128 rows x 32 k = 1024 float4 (4 per thread, along k)
    //   f = tid + i*256 : m = f>>3, kb = (f&7)*4
    // B tile: 32 k-rows x 64 n = 512 float4 (2 per thread, along n)
    //   f = tid + i*256 : k = f>>4, nb = (f&15)*4
    float4 ra[4], rb[2];

    auto loadRegs = [&](int k0) {
#pragma unroll
        for (int i = 0; i < 4; i++) {
            int f = tid + i * 256;
            int m = f >> 3, k = (f & 7) * 4;
            int gr = rowBase + m;
            ra[i] = (gr < M) ? *(const float4*)(A + (size_t)gr * K + k0 + k)
                             : make_float4(0.f, 0.f, 0.f, 0.f);
        }
#pragma unroll
        for (int i = 0; i < 2; i++) {
            int f = tid + i * 256;
            int k = f >> 4, n = (f & 15) * 4;
            rb[i] = *(const float4*)(B + (size_t)(k0 + k) * N + colBase + n);
        }
    };

    auto stSmem = [&](int buf) {
#pragma unroll
        for (int i = 0; i < 4; i++) {
            int f = tid + i * 256;
            int m = f >> 3, kb = (f & 7) * 4;
            uint32_t off = m * 32 + (kb ^ ((m & 7) * 4));
            uint4 v;
            v.x = f2tf32(ra[i].x); v.y = f2tf32(ra[i].y);
            v.z = f2tf32(ra[i].z); v.w = f2tf32(ra[i].w);
            *(uint4*)&As[buf][off] = v;
        }
#pragma unroll
        for (int i = 0; i < 2; i++) {
            int f = tid + i * 256;
            int k = f >> 4, nb = (f & 15) * 4;
            uint32_t off = k * 64 + (nb ^ ((k & 3) * 8));
            uint4 v;
            v.x = f2tf32(rb[i].x); v.y = f2tf32(rb[i].y);
            v.z = f2tf32(rb[i].z); v.w = f2tf32(rb[i].w);
            *(uint4*)&Bs[buf][off] = v;
        }
    };

    auto compute = [&](int buf) {
        const uint32_t* Ab = &As[buf][0];
        const uint32_t* Bb = &Bs[buf][0];
        int swA = gid * 4;          // row&7 == gid for all fragment rows
        int swB = tig * 8;          // k&3 == tig for both b0 (k) and b1 (k+4)
#pragma unroll
        for (int ks = 0; ks < 4; ks++) {
            uint32_t a[2][4];
            uint32_t b[4][2];
            int k0 = ks * 8 + tig;
#pragma unroll
            for (int mf = 0; mf < 2; mf++) {
                int row = (wm * 2 + mf) * 16 + gid;
                const uint32_t* r0 = Ab + row * 32;
                a[mf][0] = r0[k0 ^ swA];
                a[mf][1] = r0[256 + (k0 ^ swA)];          // +8 rows
                a[mf][2] = r0[(k0 + 4) ^ swA];
                a[mf][3] = r0[256 + ((k0 + 4) ^ swA)];
            }
#pragma unroll
            for (int nf = 0; nf < 4; nf++) {
                int col = (wn * 4 + nf) * 8 + gid;
                b[nf][0] = Bb[(ks * 8 + tig) * 64 + (col ^ swB)];
                b[nf][1] = Bb[(ks * 8 + tig + 4) * 64 + (col ^ swB)];
            }
#pragma unroll
            for (int mf = 0; mf < 2; mf++)
#pragma unroll
                for (int nf = 0; nf < 4; nf++) {
                    asm volatile(
                        "mma.sync.aligned.m16n8k8.row.col.f32.tf32.tf32.f32 "
                        "{%0,%1,%2,%3},{%4,%5,%6,%7},{%8,%9},{%0,%1,%2,%3};"
                        : "+f"(acc[mf][nf][0]), "+f"(acc[mf][nf][1]),
                          "+f"(acc[mf][nf][2]), "+f"(acc[mf][nf][3])
                        : "r"(a[mf][0]), "r"(a[mf][1]), "r"(a[mf][2]), "r"(a[mf][3]),
                          "r"(b[nf][0]), "r"(b[nf][1]));
                }
        }
    };

    loadRegs(0);
    stSmem(0);
    __syncthreads();

    int buf = 0;
    for (int k0 = 32; k0 < K; k0 += 32) {
        loadRegs(k0);
        compute(buf);
        stSmem(buf ^ 1);
        __syncthreads();
        buf ^= 1;
    }
    compute(buf);

    // Epilogue: c0/c1 contiguous (col tig*2, tig*2+1); c2/c3 at row+8.
#pragma unroll
    for (int mf = 0; mf < 2; mf++) {
        int row0 = rowBase + (wm * 2 + mf) * 16 + gid;
#pragma unroll
        for (int nf = 0; nf < 4; nf++) {
            int col = colBase + (wn * 4 + nf) * 8 + tig * 2;
            if (row0 < M)
                *(float2*)(C + (size_t)row0 * N + col) =
                    make_float2(acc[mf][nf][0], acc[mf][nf][1]);
            if (row0 + 8 < M)
                *(float2*)(C + (size_t)(row0 + 8) * N + col) =
                    make_float2(acc[mf][nf][2], acc[mf][nf][3]);
        }
    }
}

// ---------------------------------------------------------------------------
// CSR construction over the E real edges (self-loops handled inline later).
// ---------------------------------------------------------------------------
__global__ void csr_zero_kernel(int N)
{
    int i = blockIdx.x * blockDim.x + threadIdx.x;
    if (i < N) g_deg[i] = 0;
}

__global__ void csr_hist_kernel(const int* __restrict__ ei, int E)
{
    int e = blockIdx.x * blockDim.x + threadIdx.x;
    if (e < E) atomicAdd(&g_deg[ei[E + e]], 1);
}

// Single-block exclusive scan (warp shuffle + cross-warp), N up to MAXN.
__global__ __launch_bounds__(1024) void csr_scan_kernel(int N)
{
    __shared__ int wsum[32];
    __shared__ int carry;
    int tid = threadIdx.x;
    int lane = tid & 31, w = tid >> 5;
    if (tid == 0) { carry = 0; g_rowptr[0] = 0; }
    __syncthreads();
    for (int base = 0; base < N; base += 1024) {
        int i = base + tid;
        int v = (i < N) ? g_deg[i] : 0;
        int x = v;
#pragma unroll
        for (int off = 1; off < 32; off <<= 1) {
            int t = __shfl_up_sync(0xFFFFFFFF, x, off);
            if (lane >= off) x += t;
        }
        if (lane == 31) wsum[w] = x;
        __syncthreads();
        if (w == 0) {
            int s = wsum[lane];
#pragma unroll
            for (int off = 1; off < 32; off <<= 1) {
                int t = __shfl_up_sync(0xFFFFFFFF, s, off);
                if (lane >= off) s += t;
            }
            wsum[lane] = s;
        }
        __syncthreads();
        int incl = x + (w > 0 ? wsum[w - 1] : 0);
        int c = carry;
        if (i < N) {
            g_rowptr[i + 1] = c + incl;
            g_cursor[i] = c + incl - v;
        }
        __syncthreads();
        if (tid == 1023) carry = c + incl;
        __syncthreads();
    }
}

__global__ void csr_fill_kernel(const int* __restrict__ ei, int E)
{
    int e = blockIdx.x * blockDim.x + threadIdx.x;
    if (e >= E) return;
    int s = ei[e], d = ei[E + e];
    int p = atomicAdd(&g_cursor[d], 1);
    g_col[p] = s;
    g_dst[p] = d;
}

// ---------------------------------------------------------------------------
// Attention coefficients: als[n,h] = <h[n,h,:], asrc[h,:]>, same for ald.
// ---------------------------------------------------------------------------
__global__ void attn_coef_kernel(const float* __restrict__ h,
                                 const float* __restrict__ asrc,
                                 const float* __restrict__ adst,
                                 float* __restrict__ als, float* __restrict__ ald,
                                 int N, int H, int C)
{
    int idx = blockIdx.x * blockDim.x + threadIdx.x;
    if (idx >= N * H) return;
    int n = idx / H, hd = idx % H;
    const float* hp = h + (size_t)n * H * C + hd * C;
    const float* a1 = asrc + hd * C;
    const float* a2 = adst + hd * C;
    float s1 = 0.f, s2 = 0.f;
#pragma unroll 4
    for (int c = 0; c < C; c += 4) {
        float4 hv = *(const float4*)(hp + c);
        float4 v1 = *(const float4*)(a1 + c);
        float4 v2 = *(const float4*)(a2 + c);
        s1 += hv.x * v1.x + hv.y * v1.y + hv.z * v1.z + hv.w * v1.w;
        s2 += hv.x * v2.x + hv.y * v2.y + hv.z * v2.z + hv.w * v2.w;
    }
    als[idx] = s1;
    ald[idx] = s2;
}

// ---------------------------------------------------------------------------
// Edge exp: ex[p,h] = exp(leaky_relu(als[src]+ald[dst])) in CSR order.
// ---------------------------------------------------------------------------
__global__ void edge_ex4_kernel(int E, const float* __restrict__ als,
                                const float* __restrict__ ald)
{
    int p = blockIdx.x * blockDim.x + threadIdx.x;
    if (p >= E) return;
    int s = g_col[p], d = g_dst[p];
    float4 a = *(const float4*)&als[s * 4];
    float4 b = *(const float4*)&ald[d * 4];
    float4 v;
    v.x = a.x + b.x; v.x = (v.x > 0.f) ? v.x : 0.2f * v.x; v.x = __expf(v.x);
    v.y = a.y + b.y; v.y = (v.y > 0.f) ? v.y : 0.2f * v.y; v.y = __expf(v.y);
    v.z = a.z + b.z; v.z = (v.z > 0.f) ? v.z : 0.2f * v.z; v.z = __expf(v.z);
    v.w = a.w + b.w; v.w = (v.w > 0.f) ? v.w : 0.2f * v.w; v.w = __expf(v.w);
    *(float4*)&g_ex[(size_t)p * 4] = v;
}

__global__ void edge_ex1_kernel(int E, const float* __restrict__ als,
                                const float* __restrict__ ald)
{
    int p = blockIdx.x * blockDim.x + threadIdx.x;
    if (p >= E) return;
    float v = als[g_col[p]] + ald[g_dst[p]];
    v = (v > 0.f) ? v : 0.2f * v;
    g_ex[p] = __expf(v);
}

// ---------------------------------------------------------------------------
// Gather + softmax-normalize + bias + ELU, fused. One dst per TPE threads.
// ---------------------------------------------------------------------------
template <int H, int C>
__global__ __launch_bounds__(256) void gather_kernel(
    int N, const float* __restrict__ h,
    const float* __restrict__ als, const float* __restrict__ ald,
    const float* __restrict__ bias, float* __restrict__ out)
{
    constexpr int HC = H * C;
    constexpr int TPE = HC / 4;
    constexpr int DPB = 256 / TPE;
    int d = blockIdx.x * DPB + threadIdx.x / TPE;
    if (d >= N) return;
    int t = threadIdx.x % TPE;
    int hd = t / (C / 4);

    // self-loop
    float l = als[d * H + hd] + ald[d * H + hd];
    l = (l > 0.f) ? l : 0.2f * l;
    float exs = __expf(l);
    float4 hv = *(const float4*)(h + (size_t)d * HC + t * 4);
    float4 acc = make_float4(exs * hv.x, exs * hv.y, exs * hv.z, exs * hv.w);
    float den = exs;

    int p = g_rowptr[d], pend = g_rowptr[d + 1];
#pragma unroll 2
    for (; p < pend; p++) {
        int s = g_col[p];
        float ex = g_ex[(size_t)p * H + hd];
        float4 v = *(const float4*)(h + (size_t)s * HC + t * 4);
        acc.x += ex * v.x; acc.y += ex * v.y;
        acc.z += ex * v.z; acc.w += ex * v.w;
        den += ex;
    }
    float inv = 1.f / (den + 1e-16f);
    float4 bv = *(const float4*)(bias + t * 4);
    float4 o;
    o.x = acc.x * inv + bv.x; o.x = (o.x > 0.f) ? o.x : expm1f(o.x);
    o.y = acc.y * inv + bv.y; o.y = (o.y > 0.f) ? o.y : expm1f(o.y);
    o.z = acc.z * inv + bv.z; o.z = (o.z > 0.f) ? o.z : expm1f(o.z);
    o.w = acc.w * inv + bv.w; o.w = (o.w > 0.f) ? o.w : expm1f(o.w);
    *(float4*)(out + (size_t)d * HC + t * 4) = o;
}

// ---------------------------------------------------------------------------
// Pooling (batch is sorted): run-length local accumulate, rare atomic flush.
// ---------------------------------------------------------------------------
__global__ void pool_init_kernel()
{
    int idx = blockIdx.x * blockDim.x + threadIdx.x;
    if (idx < 64 * 64) g_pool[idx] = 0.f;
    if (idx < 64) g_cnt[idx] = 0.f;
}

__global__ __launch_bounds__(256) void pool_acc_kernel(
    const float* __restrict__ h, const int* __restrict__ batch, int N)
{
    int c = threadIdx.x & 63;
    int lane = threadIdx.x >> 6;
    int n0 = blockIdx.x * 64 + lane * 16;
    float acc = 0.f;
    int curg = -1, cnt = 0;
    for (int k = 0; k < 16; k++) {
        int n = n0 + k;
        if (n >= N) break;
        int g = batch[n];
        if (g != curg) {
            if (curg >= 0) {
                atomicAdd(&g_pool[curg * 64 + c], acc);
                if (c == 0) atomicAdd(&g_cnt[curg], (float)cnt);
            }
            curg = g; acc = 0.f; cnt = 0;
        }
        acc += h[(size_t)n * 64 + c];
        cnt++;
    }
    if (curg >= 0) {
        atomicAdd(&g_pool[curg * 64 + c], acc);
        if (c == 0) atomicAdd(&g_cnt[curg], (float)cnt);
    }
}

__global__ void final_linear_kernel(const float* __restrict__ linW,
                                    const float* __restrict__ linb,
                                    float* __restrict__ out)
{
    int idx = blockIdx.x * blockDim.x + threadIdx.x;
    if (idx >= 64 * 10) return;
    int g = idx / 10, o = idx % 10;
    float inv = 1.f / fmaxf(g_cnt[g], 1.f);
    float s = 0.f;
#pragma unroll 8
    for (int k = 0; k < 64; k++)
        s += g_pool[g * 64 + k] * inv * linW[k * 10 + o];
    out[idx] = s + linb[o];
}

// ---------------------------------------------------------------------------
// Host orchestration (graph-capturable: kernel launches only)
// ---------------------------------------------------------------------------
static void run_layer(const float* in, int Kdim,
                      const float* W, const float* b,
                      const float* asrc, const float* adst,
                      int H, int C, int N, int E,
                      float* hA, float* hOut, float* als, float* ald)
{
    int HC = H * C;
    {
        dim3 grid(HC / 64, (N + 127) / 128);
        tf32_gemm_kernel<<<grid, 256>>>(in, W, hA, N, HC, Kdim);
    }
    attn_coef_kernel<<<(N * H + 255) / 256, 256>>>(hA, asrc, adst, als, ald, N, H, C);
    if (H == 4) {
        edge_ex4_kernel<<<(E + 255) / 256, 256>>>(E, als, ald);
        gather_kernel<4, 64><<<(N + 3) / 4, 256>>>(N, hA, als, ald, b, hOut);
    } else {
        edge_ex1_kernel<<<(E + 255) / 256, 256>>>(E, als, ald);
        gather_kernel<1, 64><<<(N + 15) / 16, 256>>>(N, hA, als, ald, b, hOut);
    }
}

extern "C" void kernel_launch(void* const* d_in, const int* in_sizes, int n_in,
                              void* d_out, int out_size)
{
    const float* x     = (const float*)d_in[0];
    const int*   ei    = (const int*)d_in[1];
    const int*   batch = (const int*)d_in[2];
    const float* W1 = (const float*)d_in[3];   const float* b1 = (const float*)d_in[4];
    const float* as1 = (const float*)d_in[5];  const float* ad1 = (const float*)d_in[6];
    const float* W2 = (const float*)d_in[7];   const float* b2 = (const float*)d_in[8];
    const float* as2 = (const float*)d_in[9];  const float* ad2 = (const float*)d_in[10];
    const float* W3 = (const float*)d_in[11];  const float* b3 = (const float*)d_in[12];
    const float* as3 = (const float*)d_in[13]; const float* ad3 = (const float*)d_in[14];
    const float* linW = (const float*)d_in[15]; const float* linb = (const float*)d_in[16];
    float* out = (float*)d_out;

    int N = in_sizes[0] / 128;
    int E = in_sizes[1] / 2;

    float *hA, *hB, *als, *ald;
    cudaGetSymbolAddress((void**)&hA,  g_hA);
    cudaGetSymbolAddress((void**)&hB,  g_hB);
    cudaGetSymbolAddress((void**)&als, g_als);
    cudaGetSymbolAddress((void**)&ald, g_ald);

    // CSR build (once; edges identical across layers)
    csr_zero_kernel<<<(N + 255) / 256, 256>>>(N);
    csr_hist_kernel<<<(E + 255) / 256, 256>>>(ei, E);
    csr_scan_kernel<<<1, 1024>>>(N);
    csr_fill_kernel<<<(E + 255) / 256, 256>>>(ei, E);

    // Layer 1: x[N,128] -> hB[N,256]
    run_layer(x, 128, W1, b1, as1, ad1, 4, 64, N, E, hA, hB, als, ald);
    // Layer 2: hB[N,256] -> hB[N,256]
    run_layer(hB, 256, W2, b2, as2, ad2, 4, 64, N, E, hA, hB, als, ald);
    // Layer 3: hB[N,256] -> hB[N,64]
    run_layer(hB, 256, W3, b3, as3, ad3, 1, 64, N, E, hA, hB, als, ald);

    // Pool + final linear
    pool_init_kernel<<<(64 * 64 + 255) / 256, 256>>>();
    pool_acc_kernel<<<(N + 63) / 64, 256>>>(hB, batch, N);
    final_linear_kernel<<<3, 256>>>(linW, linb, out);
}

// round 6
// speedup vs baseline: 2.5213x; 1.1476x over previous
#include <cuda_runtime.h>
#include <math.h>
#include <stdint.h>

// ---------------------------------------------------------------------------
// Problem constants: N=50000, E=600000, IN=128, HID=64, HEADS=4, OUT=10, G=64
// ---------------------------------------------------------------------------
#define MAXN 50048
#define MAXE 600064

// Scratch (device globals — no allocations allowed)
__device__ __align__(16) float g_hA[(size_t)MAXN * 256];   // GEMM output h
__device__ __align__(16) float g_hB[(size_t)MAXN * 256];   // layer activations
__device__ __align__(16) float g_ex[(size_t)MAXE * 4];     // CSR-ordered exp(logit)
__device__ __align__(16) float g_als[(size_t)MAXN * 4];    // alpha_src coeffs
__device__ __align__(16) float g_ald[(size_t)MAXN * 4];    // alpha_dst coeffs
__device__ int g_deg[MAXN];
__device__ int g_rowptr[MAXN + 1];
__device__ int g_cursor[MAXN];
__device__ int g_col[MAXE];        // src per CSR slot
__device__ int g_dst[MAXE];        // dst per CSR slot
__device__ __align__(16) float g_pool[64 * 64];
__device__ __align__(16) float g_cnt[64];

// ---------------------------------------------------------------------------
// TF32 tensor-core GEMM with fused attention-coefficient epilogue.
// C[M,N] = A[M,K] @ B[K,N]; als[m,hd] = <C_row_head, asrc[hd]>, same ald.
// BM=128, BN=64(=one head), BK=32. 8 warps; warp tile 32x32.
// Smem: row-major XOR-swizzled tiles; conflict-free STS.128 and LDS.
// Requires: N % 64 == 0, K % 32 == 0 (holds: 64/128/256).
// ---------------------------------------------------------------------------
__device__ __forceinline__ uint32_t f2tf32(float x)
{
    uint32_t r;
    asm("cvt.rna.tf32.f32 %0, %1;" : "=r"(r) : "f"(x));
    return r;
}

__global__ __launch_bounds__(256) void tf32_gemm_kernel(
    const float* __restrict__ A, const float* __restrict__ B,
    float* __restrict__ C, int M, int N, int K,
    const float* __restrict__ asrc, const float* __restrict__ adst,
    float* __restrict__ als, float* __restrict__ ald, int H)
{
    __shared__ uint32_t As[2][4096];   // 128 x 32, swizzled
    __shared__ uint32_t Bs[2][2048];   // 32 x 64, swizzled

    int tid = threadIdx.x;
    int warp = tid >> 5, lane = tid & 31;
    int gid = lane >> 2, tig = lane & 3;
    int wm = warp & 3, wn = warp >> 2;           // wm 0..3 (M), wn 0..1 (N)
    int rowBase = blockIdx.y * 128;
    int colBase = blockIdx.x * 64;

    float acc[2][4][4];
#pragma unroll
    for (int i = 0; i < 2; i++)
#pragma unroll
        for (int j = 0; j < 4; j++)
#pragma unroll
            for (int r = 0; r < 4; r++) acc[i][j][r] = 0.f;

    float4 ra[4], rb[2];

    auto loadRegs = [&](int k0) {
#pragma unroll
        for (int i = 0; i < 4; i++) {
            int f = tid + i * 256;
            int m = f >> 3, k = (f & 7) * 4;
            int gr = rowBase + m;
            ra[i] = (gr < M) ? *(const float4*)(A + (size_t)gr * K + k0 + k)
                             : make_float4(0.f, 0.f, 0.f, 0.f);
        }
#pragma unroll
        for (int i = 0; i < 2; i++) {
            int f = tid + i * 256;
            int k = f >> 4, n = (f & 15) * 4;
            rb[i] = *(const float4*)(B + (size_t)(k0 + k) * N + colBase + n);
        }
    };

    auto stSmem = [&](int buf) {
#pragma unroll
        for (int i = 0; i < 4; i++) {
            int f = tid + i * 256;
            int m = f >> 3, kb = (f & 7) * 4;
            uint32_t off = m * 32 + (kb ^ ((m & 7) * 4));
            uint4 v;
            v.x = f2tf32(ra[i].x); v.y = f2tf32(ra[i].y);
            v.z = f2tf32(ra[i].z); v.w = f2tf32(ra[i].w);
            *(uint4*)&As[buf][off] = v;
        }
#pragma unroll
        for (int i = 0; i < 2; i++) {
            int f = tid + i * 256;
            int k = f >> 4, nb = (f & 15) * 4;
            uint32_t off = k * 64 + (nb ^ ((k & 3) * 8));
            uint4 v;
            v.x = f2tf32(rb[i].x); v.y = f2tf32(rb[i].y);
            v.z = f2tf32(rb[i].z); v.w = f2tf32(rb[i].w);
            *(uint4*)&Bs[buf][off] = v;
        }
    };

    auto compute = [&](int buf) {
        const uint32_t* Ab = &As[buf][0];
        const uint32_t* Bb = &Bs[buf][0];
        int swA = gid * 4;
        int swB = tig * 8;
#pragma unroll
        for (int ks = 0; ks < 4; ks++) {
            uint32_t a[2][4];
            uint32_t b[4][2];
            int k0 = ks * 8 + tig;
#pragma unroll
            for (int mf = 0; mf < 2; mf++) {
                int row = (wm * 2 + mf) * 16 + gid;
                const uint32_t* r0 = Ab + row * 32;
                a[mf][0] = r0[k0 ^ swA];
                a[mf][1] = r0[256 + (k0 ^ swA)];          // +8 rows
                a[mf][2] = r0[(k0 + 4) ^ swA];
                a[mf][3] = r0[256 + ((k0 + 4) ^ swA)];
            }
#pragma unroll
            for (int nf = 0; nf < 4; nf++) {
                int col = (wn * 4 + nf) * 8 + gid;
                b[nf][0] = Bb[(ks * 8 + tig) * 64 + (col ^ swB)];
                b[nf][1] = Bb[(ks * 8 + tig + 4) * 64 + (col ^ swB)];
            }
#pragma unroll
            for (int mf = 0; mf < 2; mf++)
#pragma unroll
                for (int nf = 0; nf < 4; nf++) {
                    asm volatile(
                        "mma.sync.aligned.m16n8k8.row.col.f32.tf32.tf32.f32 "
                        "{%0,%1,%2,%3},{%4,%5,%6,%7},{%8,%9},{%0,%1,%2,%3};"
                        : "+f"(acc[mf][nf][0]), "+f"(acc[mf][nf][1]),
                          "+f"(acc[mf][nf][2]), "+f"(acc[mf][nf][3])
                        : "r"(a[mf][0]), "r"(a[mf][1]), "r"(a[mf][2]), "r"(a[mf][3]),
                          "r"(b[nf][0]), "r"(b[nf][1]));
                }
        }
    };

    loadRegs(0);
    stSmem(0);
    __syncthreads();

    int buf = 0;
    for (int k0 = 32; k0 < K; k0 += 32) {
        loadRegs(k0);
        compute(buf);
        stSmem(buf ^ 1);
        __syncthreads();
        buf ^= 1;
    }
    compute(buf);

    // C store: c0/c1 at (row0, col..col+1); c2/c3 at row0+8.
#pragma unroll
    for (int mf = 0; mf < 2; mf++) {
        int row0 = rowBase + (wm * 2 + mf) * 16 + gid;
#pragma unroll
        for (int nf = 0; nf < 4; nf++) {
            int col = colBase + (wn * 4 + nf) * 8 + tig * 2;
            if (row0 < M)
                *(float2*)(C + (size_t)row0 * N + col) =
                    make_float2(acc[mf][nf][0], acc[mf][nf][1]);
            if (row0 + 8 < M)
                *(float2*)(C + (size_t)(row0 + 8) * N + col) =
                    make_float2(acc[mf][nf][2], acc[mf][nf][3]);
        }
    }

    // ---- fused attn-coef epilogue: als/ald row dots for this head ----
    {
        int hd = blockIdx.x;                       // BN == C == 64
        const float* ah = asrc + hd * 64;
        const float* dh = adst + hd * 64;
        float* sred = (float*)&As[buf ^ 1][0];     // free buffer: 128 x 2 floats
        float ps[2][2][2];                         // [mf][half][src/dst]
#pragma unroll
        for (int mf = 0; mf < 2; mf++) {
            float s0 = 0.f, s1 = 0.f, t0 = 0.f, t1 = 0.f;
#pragma unroll
            for (int nf = 0; nf < 4; nf++) {
                int l = (wn * 4 + nf) * 8 + tig * 2;
                float a0 = ah[l], a1 = ah[l + 1];
                float d0 = dh[l], d1 = dh[l + 1];
                s0 += acc[mf][nf][0] * a0 + acc[mf][nf][1] * a1;
                s1 += acc[mf][nf][2] * a0 + acc[mf][nf][3] * a1;
                t0 += acc[mf][nf][0] * d0 + acc[mf][nf][1] * d1;
                t1 += acc[mf][nf][2] * d0 + acc[mf][nf][3] * d1;
            }
            ps[mf][0][0] = s0; ps[mf][1][0] = s1;
            ps[mf][0][1] = t0; ps[mf][1][1] = t1;
        }
#pragma unroll
        for (int mf = 0; mf < 2; mf++)
#pragma unroll
            for (int hf = 0; hf < 2; hf++)
#pragma unroll
                for (int q = 0; q < 2; q++) {
                    ps[mf][hf][q] += __shfl_xor_sync(0xFFFFFFFF, ps[mf][hf][q], 1);
                    ps[mf][hf][q] += __shfl_xor_sync(0xFFFFFFFF, ps[mf][hf][q], 2);
                }
        if (tig == 0 && wn == 0) {
#pragma unroll
            for (int mf = 0; mf < 2; mf++)
#pragma unroll
                for (int hf = 0; hf < 2; hf++) {
                    int rl = (wm * 2 + mf) * 16 + hf * 8 + gid;
                    sred[rl * 2 + 0] = ps[mf][hf][0];
                    sred[rl * 2 + 1] = ps[mf][hf][1];
                }
        }
        __syncthreads();
        if (tig == 0 && wn == 1) {
#pragma unroll
            for (int mf = 0; mf < 2; mf++)
#pragma unroll
                for (int hf = 0; hf < 2; hf++) {
                    int rl = (wm * 2 + mf) * 16 + hf * 8 + gid;
                    int row = rowBase + rl;
                    if (row < M) {
                        als[row * H + hd] = ps[mf][hf][0] + sred[rl * 2 + 0];
                        ald[row * H + hd] = ps[mf][hf][1] + sred[rl * 2 + 1];
                    }
                }
        }
    }
}

// ---------------------------------------------------------------------------
// Init: zero degree histogram + pooling accumulators (one launch).
// ---------------------------------------------------------------------------
__global__ void init_kernel(int N)
{
    int i = blockIdx.x * blockDim.x + threadIdx.x;
    if (i < N) g_deg[i] = 0;
    if (i < 64 * 64) g_pool[i] = 0.f;
    if (i < 64) g_cnt[i] = 0.f;
}

__global__ void csr_hist_kernel(const int* __restrict__ ei, int E)
{
    int e = blockIdx.x * blockDim.x + threadIdx.x;
    if (e < E) atomicAdd(&g_deg[ei[E + e]], 1);
}

// Single-block exclusive scan (warp shuffle + cross-warp), N up to MAXN.
__global__ __launch_bounds__(1024) void csr_scan_kernel(int N)
{
    __shared__ int wsum[32];
    __shared__ int carry;
    int tid = threadIdx.x;
    int lane = tid & 31, w = tid >> 5;
    if (tid == 0) { carry = 0; g_rowptr[0] = 0; }
    __syncthreads();
    for (int base = 0; base < N; base += 1024) {
        int i = base + tid;
        int v = (i < N) ? g_deg[i] : 0;
        int x = v;
#pragma unroll
        for (int off = 1; off < 32; off <<= 1) {
            int t = __shfl_up_sync(0xFFFFFFFF, x, off);
            if (lane >= off) x += t;
        }
        if (lane == 31) wsum[w] = x;
        __syncthreads();
        if (w == 0) {
            int s = wsum[lane];
#pragma unroll
            for (int off = 1; off < 32; off <<= 1) {
                int t = __shfl_up_sync(0xFFFFFFFF, s, off);
                if (lane >= off) s += t;
            }
            wsum[lane] = s;
        }
        __syncthreads();
        int incl = x + (w > 0 ? wsum[w - 1] : 0);
        int c = carry;
        if (i < N) {
            g_rowptr[i + 1] = c + incl;
            g_cursor[i] = c + incl - v;
        }
        __syncthreads();
        if (tid == 1023) carry = c + incl;
        __syncthreads();
    }
}

__global__ void csr_fill_kernel(const int* __restrict__ ei, int E)
{
    int e = blockIdx.x * blockDim.x + threadIdx.x;
    if (e >= E) return;
    int s = ei[e], d = ei[E + e];
    int p = atomicAdd(&g_cursor[d], 1);
    g_col[p] = s;
    g_dst[p] = d;
}

// ---------------------------------------------------------------------------
// Edge exp: ex[p,h] = exp(leaky_relu(als[src]+ald[dst])) in CSR order.
// ---------------------------------------------------------------------------
__global__ void edge_ex4_kernel(int E, const float* __restrict__ als,
                                const float* __restrict__ ald)
{
    int p = blockIdx.x * blockDim.x + threadIdx.x;
    if (p >= E) return;
    int s = g_col[p], d = g_dst[p];
    float4 a = *(const float4*)&als[s * 4];
    float4 b = *(const float4*)&ald[d * 4];
    float4 v;
    v.x = a.x + b.x; v.x = (v.x > 0.f) ? v.x : 0.2f * v.x; v.x = __expf(v.x);
    v.y = a.y + b.y; v.y = (v.y > 0.f) ? v.y : 0.2f * v.y; v.y = __expf(v.y);
    v.z = a.z + b.z; v.z = (v.z > 0.f) ? v.z : 0.2f * v.z; v.z = __expf(v.z);
    v.w = a.w + b.w; v.w = (v.w > 0.f) ? v.w : 0.2f * v.w; v.w = __expf(v.w);
    *(float4*)&g_ex[(size_t)p * 4] = v;
}

__global__ void edge_ex1_kernel(int E, const float* __restrict__ als,
                                const float* __restrict__ ald)
{
    int p = blockIdx.x * blockDim.x + threadIdx.x;
    if (p >= E) return;
    float v = als[g_col[p]] + ald[g_dst[p]];
    v = (v > 0.f) ? v : 0.2f * v;
    g_ex[p] = __expf(v);
}

// ---------------------------------------------------------------------------
// Gather + softmax-normalize + bias + ELU, fused. One dst per TPE threads.
// ---------------------------------------------------------------------------
template <int H, int C>
__global__ __launch_bounds__(256) void gather_kernel(
    int N, const float* __restrict__ h,
    const float* __restrict__ als, const float* __restrict__ ald,
    const float* __restrict__ bias, float* __restrict__ out)
{
    constexpr int HC = H * C;
    constexpr int TPE = HC / 4;
    constexpr int DPB = 256 / TPE;
    int d = blockIdx.x * DPB + threadIdx.x / TPE;
    if (d >= N) return;
    int t = threadIdx.x % TPE;
    int hd = t / (C / 4);

    // self-loop
    float l = als[d * H + hd] + ald[d * H + hd];
    l = (l > 0.f) ? l : 0.2f * l;
    float exs = __expf(l);
    float4 hv = *(const float4*)(h + (size_t)d * HC + t * 4);
    float4 acc = make_float4(exs * hv.x, exs * hv.y, exs * hv.z, exs * hv.w);
    float den = exs;

    int p = g_rowptr[d], pend = g_rowptr[d + 1];
#pragma unroll 2
    for (; p < pend; p++) {
        int s = g_col[p];
        float ex = g_ex[(size_t)p * H + hd];
        float4 v = *(const float4*)(h + (size_t)s * HC + t * 4);
        acc.x += ex * v.x; acc.y += ex * v.y;
        acc.z += ex * v.z; acc.w += ex * v.w;
        den += ex;
    }
    float inv = 1.f / (den + 1e-16f);
    float4 bv = *(const float4*)(bias + t * 4);
    float4 o;
    o.x = acc.x * inv + bv.x; o.x = (o.x > 0.f) ? o.x : expm1f(o.x);
    o.y = acc.y * inv + bv.y; o.y = (o.y > 0.f) ? o.y : expm1f(o.y);
    o.z = acc.z * inv + bv.z; o.z = (o.z > 0.f) ? o.z : expm1f(o.z);
    o.w = acc.w * inv + bv.w; o.w = (o.w > 0.f) ? o.w : expm1f(o.w);
    *(float4*)(out + (size_t)d * HC + t * 4) = o;
}

// ---------------------------------------------------------------------------
// Pooling (batch is sorted): run-length local accumulate, rare atomic flush.
// ---------------------------------------------------------------------------
__global__ __launch_bounds__(256) void pool_acc_kernel(
    const float* __restrict__ h, const int* __restrict__ batch, int N)
{
    int c = threadIdx.x & 63;
    int lane = threadIdx.x >> 6;
    int n0 = blockIdx.x * 64 + lane * 16;
    float acc = 0.f;
    int curg = -1, cnt = 0;
    for (int k = 0; k < 16; k++) {
        int n = n0 + k;
        if (n >= N) break;
        int g = batch[n];
        if (g != curg) {
            if (curg >= 0) {
                atomicAdd(&g_pool[curg * 64 + c], acc);
                if (c == 0) atomicAdd(&g_cnt[curg], (float)cnt);
            }
            curg = g; acc = 0.f; cnt = 0;
        }
        acc += h[(size_t)n * 64 + c];
        cnt++;
    }
    if (curg >= 0) {
        atomicAdd(&g_pool[curg * 64 + c], acc);
        if (c == 0) atomicAdd(&g_cnt[curg], (float)cnt);
    }
}

__global__ void final_linear_kernel(const float* __restrict__ linW,
                                    const float* __restrict__ linb,
                                    float* __restrict__ out)
{
    int idx = blockIdx.x * blockDim.x + threadIdx.x;
    if (idx >= 64 * 10) return;
    int g = idx / 10, o = idx % 10;
    float inv = 1.f / fmaxf(g_cnt[g], 1.f);
    float s = 0.f;
#pragma unroll 8
    for (int k = 0; k < 64; k++)
        s += g_pool[g * 64 + k] * inv * linW[k * 10 + o];
    out[idx] = s + linb[o];
}

// ---------------------------------------------------------------------------
// Host orchestration (graph-capturable: kernel launches only).
// NOTE: the layer-1 GEMM is deliberately user launch #4 (the one ncu
// captures under the harness's -s 5 -c 1) so we get its roofline.
// ---------------------------------------------------------------------------
extern "C" void kernel_launch(void* const* d_in, const int* in_sizes, int n_in,
                              void* d_out, int out_size)
{
    const float* x     = (const float*)d_in[0];
    const int*   ei    = (const int*)d_in[1];
    const int*   batch = (const int*)d_in[2];
    const float* W1 = (const float*)d_in[3];   const float* b1 = (const float*)d_in[4];
    const float* as1 = (const float*)d_in[5];  const float* ad1 = (const float*)d_in[6];
    const float* W2 = (const float*)d_in[7];   const float* b2 = (const float*)d_in[8];
    const float* as2 = (const float*)d_in[9];  const float* ad2 = (const float*)d_in[10];
    const float* W3 = (const float*)d_in[11];  const float* b3 = (const float*)d_in[12];
    const float* as3 = (const float*)d_in[13]; const float* ad3 = (const float*)d_in[14];
    const float* linW = (const float*)d_in[15]; const float* linb = (const float*)d_in[16];
    float* out = (float*)d_out;

    int N = in_sizes[0] / 128;
    int E = in_sizes[1] / 2;

    float *hA, *hB, *als, *ald;
    cudaGetSymbolAddress((void**)&hA,  g_hA);
    cudaGetSymbolAddress((void**)&hB,  g_hB);
    cudaGetSymbolAddress((void**)&als, g_als);
    cudaGetSymbolAddress((void**)&ald, g_ald);

    int gemmRows = (N + 127) / 128;

    // 1-3: CSR prep (fill deferred past the gemm so gemm is launch #4)
    init_kernel<<<(N + 255) / 256, 256>>>(N);
    csr_hist_kernel<<<(E + 255) / 256, 256>>>(ei, E);
    csr_scan_kernel<<<1, 1024>>>(N);

    // 4: layer-1 GEMM (+ fused attn coefs)   <-- profiled launch
    tf32_gemm_kernel<<<dim3(4, gemmRows), 256>>>(x, W1, hA, N, 256, 128,
                                                 as1, ad1, als, ald, 4);
    // 5: finish CSR
    csr_fill_kernel<<<(E + 255) / 256, 256>>>(ei, E);

    // Layer 1 edge phase
    edge_ex4_kernel<<<(E + 255) / 256, 256>>>(E, als, ald);
    gather_kernel<4, 64><<<(N + 3) / 4, 256>>>(N, hA, als, ald, b1, hB);

    // Layer 2
    tf32_gemm_kernel<<<dim3(4, gemmRows), 256>>>(hB, W2, hA, N, 256, 256,
                                                 as2, ad2, als, ald, 4);
    edge_ex4_kernel<<<(E + 255) / 256, 256>>>(E, als, ald);
    gather_kernel<4, 64><<<(N + 3) / 4, 256>>>(N, hA, als, ald, b2, hB);

    // Layer 3
    tf32_gemm_kernel<<<dim3(1, gemmRows), 256>>>(hB, W3, hA, N, 64, 256,
                                                 as3, ad3, als, ald, 1);
    edge_ex1_kernel<<<(E + 255) / 256, 256>>>(E, als, ald);
    gather_kernel<1, 64><<<(N + 15) / 16, 256>>>(N, hA, als, ald, b3, hB);

    // Pool + final linear
    pool_acc_kernel<<<(N + 63) / 64, 256>>>(hB, batch, N);
    final_linear_kernel<<<3, 256>>>(linW, linb, out);
}

// round 7
// speedup vs baseline: 3.3653x; 1.3347x over previous
#include <cuda_runtime.h>
#include <math.h>
#include <stdint.h>

// ---------------------------------------------------------------------------
// Problem constants: N=50000, E=600000, IN=128, HID=64, HEADS=4, OUT=10, G=64
// ---------------------------------------------------------------------------
#define MAXN 50048
#define MAXE 600064

// Scratch (device globals — no allocations allowed)
__device__ __align__(16) float g_hA[(size_t)MAXN * 256];   // GEMM output h
__device__ __align__(16) float g_hB[(size_t)MAXN * 256];   // layer activations
__device__ __align__(16) float g_xc[(size_t)MAXN * 128];   // tf32-rounded x
__device__ __align__(16) float g_Wc[114688];               // tf32-rounded W1|W2|W3
__device__ __align__(16) float g_ex[(size_t)MAXE * 4];     // CSR-ordered exp(logit)
__device__ __align__(16) float g_als[(size_t)MAXN * 4];    // alpha_src coeffs
__device__ __align__(16) float g_ald[(size_t)MAXN * 4];    // alpha_dst coeffs
__device__ int g_deg[MAXN];
__device__ int g_rowptr[MAXN + 1];
__device__ int g_cursor[MAXN];
__device__ int g_col[MAXE];        // src per CSR slot
__device__ int g_dst[MAXE];        // dst per CSR slot
__device__ __align__(16) float g_pool[64 * 64];
__device__ __align__(16) float g_cnt[64];

__device__ __forceinline__ uint32_t f2tf32(float x)
{
    uint32_t r;
    asm("cvt.rna.tf32.f32 %0, %1;" : "=r"(r) : "f"(x));
    return r;
}

// ---------------------------------------------------------------------------
// tf32-RNA rounding pre-passes (inputs to the async GEMM must be pre-rounded:
// cp.async copies raw bits and the MMA truncates, so rounding is hoisted here).
// ---------------------------------------------------------------------------
__global__ void convert_x_kernel(const float* __restrict__ in,
                                 float* __restrict__ out, int n4)
{
    int i = blockIdx.x * blockDim.x + threadIdx.x;
    if (i >= n4) return;
    float4 v = ((const float4*)in)[i];
    float4 o;
    o.x = __uint_as_float(f2tf32(v.x));
    o.y = __uint_as_float(f2tf32(v.y));
    o.z = __uint_as_float(f2tf32(v.z));
    o.w = __uint_as_float(f2tf32(v.w));
    ((float4*)out)[i] = o;
}

// W1 (128x256) -> [0:32768), W2 (256x256) -> [32768:98304), W3 (256x64) -> [98304:114688)
__global__ void convert_w_kernel(const float* __restrict__ W1,
                                 const float* __restrict__ W2,
                                 const float* __restrict__ W3)
{
    int i = blockIdx.x * blockDim.x + threadIdx.x;   // float4 index, 28672 total
    if (i >= 28672) return;
    const float* src;
    int j;
    if (i < 8192)       { src = W1; j = i; }
    else if (i < 24576) { src = W2; j = i - 8192; }
    else                { src = W3; j = i - 24576; }
    float4 v = ((const float4*)src)[j];
    float4 o;
    o.x = __uint_as_float(f2tf32(v.x));
    o.y = __uint_as_float(f2tf32(v.y));
    o.z = __uint_as_float(f2tf32(v.z));
    o.w = __uint_as_float(f2tf32(v.w));
    ((float4*)g_Wc)[i] = o;
}

// ---------------------------------------------------------------------------
// TF32 tensor-core GEMM, cp.async 2-stage pipeline, fused attn-coef epilogue.
// Inputs A, B MUST be tf32-RNA-pre-rounded fp32.
// BM=128, BN=64(=one head), BK=32. 8 warps; warp tile 32x32.
// Smem row-major XOR-swizzled; conflict-free cp.async stores and LDS reads.
// ---------------------------------------------------------------------------
__global__ __launch_bounds__(256) void tf32_gemm_kernel(
    const float* __restrict__ A, const float* __restrict__ B,
    float* __restrict__ C, int M, int N, int K,
    const float* __restrict__ asrc, const float* __restrict__ adst,
    float* __restrict__ als, float* __restrict__ ald, int H)
{
    __shared__ uint32_t As[2][4096];   // 128 x 32, swizzled
    __shared__ uint32_t Bs[2][2048];   // 32 x 64, swizzled

    int tid = threadIdx.x;
    int warp = tid >> 5, lane = tid & 31;
    int gid = lane >> 2, tig = lane & 3;
    int wm = warp & 3, wn = warp >> 2;           // wm 0..3 (M), wn 0..1 (N)
    int rowBase = blockIdx.y * 128;
    int colBase = blockIdx.x * 64;

    uint32_t asBase, bsBase;
    {
        asm("{ .reg .u64 t; cvta.to.shared.u64 t, %1; cvt.u32.u64 %0, t; }"
            : "=r"(asBase) : "l"(&As[0][0]));
        asm("{ .reg .u64 t; cvta.to.shared.u64 t, %1; cvt.u32.u64 %0, t; }"
            : "=r"(bsBase) : "l"(&Bs[0][0]));
    }

    float acc[2][4][4];
#pragma unroll
    for (int i = 0; i < 2; i++)
#pragma unroll
        for (int j = 0; j < 4; j++)
#pragma unroll
            for (int r = 0; r < 4; r++) acc[i][j][r] = 0.f;

    // A tile: f = tid + i*256 : m = f>>3, kb = (f&7)*4 (one float4 each)
    // B tile: f = tid + i*256 : k = f>>4, nb = (f&15)*4
    auto issue = [&](int k0, int buf) {
#pragma unroll
        for (int i = 0; i < 4; i++) {
            int f = tid + i * 256;
            int m = f >> 3, kb = (f & 7) * 4;
            uint32_t off = m * 32 + (kb ^ ((m & 7) * 4));
            int gr = rowBase + m;
            const float* src = A + (size_t)(gr < M ? gr : M - 1) * K + k0 + kb;
            int sz = (gr < M) ? 16 : 0;
            uint32_t dst = asBase + (buf * 4096 + off) * 4;
            asm volatile("cp.async.cg.shared.global [%0], [%1], 16, %2;"
                         :: "r"(dst), "l"(src), "r"(sz));
        }
#pragma unroll
        for (int i = 0; i < 2; i++) {
            int f = tid + i * 256;
            int k = f >> 4, nb = (f & 15) * 4;
            uint32_t off = k * 64 + (nb ^ ((k & 3) * 8));
            const float* src = B + (size_t)(k0 + k) * N + colBase + nb;
            uint32_t dst = bsBase + (buf * 2048 + off) * 4;
            asm volatile("cp.async.cg.shared.global [%0], [%1], 16;"
                         :: "r"(dst), "l"(src));
        }
        asm volatile("cp.async.commit_group;");
    };

    auto compute = [&](int buf) {
        const uint32_t* Ab = &As[buf][0];
        const uint32_t* Bb = &Bs[buf][0];
        int swA = gid * 4;
        int swB = tig * 8;
#pragma unroll
        for (int ks = 0; ks < 4; ks++) {
            uint32_t a[2][4];
            uint32_t b[4][2];
            int k0 = ks * 8 + tig;
#pragma unroll
            for (int mf = 0; mf < 2; mf++) {
                int row = (wm * 2 + mf) * 16 + gid;
                const uint32_t* r0 = Ab + row * 32;
                a[mf][0] = r0[k0 ^ swA];
                a[mf][1] = r0[256 + (k0 ^ swA)];          // +8 rows
                a[mf][2] = r0[(k0 + 4) ^ swA];
                a[mf][3] = r0[256 + ((k0 + 4) ^ swA)];
            }
#pragma unroll
            for (int nf = 0; nf < 4; nf++) {
                int col = (wn * 4 + nf) * 8 + gid;
                b[nf][0] = Bb[(ks * 8 + tig) * 64 + (col ^ swB)];
                b[nf][1] = Bb[(ks * 8 + tig + 4) * 64 + (col ^ swB)];
            }
#pragma unroll
            for (int mf = 0; mf < 2; mf++)
#pragma unroll
                for (int nf = 0; nf < 4; nf++) {
                    asm volatile(
                        "mma.sync.aligned.m16n8k8.row.col.f32.tf32.tf32.f32 "
                        "{%0,%1,%2,%3},{%4,%5,%6,%7},{%8,%9},{%0,%1,%2,%3};"
                        : "+f"(acc[mf][nf][0]), "+f"(acc[mf][nf][1]),
                          "+f"(acc[mf][nf][2]), "+f"(acc[mf][nf][3])
                        : "r"(a[mf][0]), "r"(a[mf][1]), "r"(a[mf][2]), "r"(a[mf][3]),
                          "r"(b[nf][0]), "r"(b[nf][1]));
                }
        }
    };

    int nt = K >> 5;             // K/32 tiles
    issue(0, 0);
    int buf = 0;
    for (int t = 0; t < nt; t++) {
        if (t + 1 < nt) issue((t + 1) * 32, buf ^ 1);
        else            asm volatile("cp.async.commit_group;");
        asm volatile("cp.async.wait_group 1;");
        __syncthreads();
        compute(buf);
        __syncthreads();
        buf ^= 1;
    }

    // C store: c0/c1 at (row0, col..col+1); c2/c3 at row0+8.
#pragma unroll
    for (int mf = 0; mf < 2; mf++) {
        int row0 = rowBase + (wm * 2 + mf) * 16 + gid;
#pragma unroll
        for (int nf = 0; nf < 4; nf++) {
            int col = colBase + (wn * 4 + nf) * 8 + tig * 2;
            if (row0 < M)
                *(float2*)(C + (size_t)row0 * N + col) =
                    make_float2(acc[mf][nf][0], acc[mf][nf][1]);
            if (row0 + 8 < M)
                *(float2*)(C + (size_t)(row0 + 8) * N + col) =
                    make_float2(acc[mf][nf][2], acc[mf][nf][3]);
        }
    }

    // ---- fused attn-coef epilogue: als/ald row dots for this head ----
    {
        int hd = blockIdx.x;                       // BN == C == 64
        const float* ah = asrc + hd * 64;
        const float* dh = adst + hd * 64;
        float* sred = (float*)&As[0][0];           // post-loop: buffers free
        float ps[2][2][2];                         // [mf][half][src/dst]
#pragma unroll
        for (int mf = 0; mf < 2; mf++) {
            float s0 = 0.f, s1 = 0.f, t0 = 0.f, t1 = 0.f;
#pragma unroll
            for (int nf = 0; nf < 4; nf++) {
                int l = (wn * 4 + nf) * 8 + tig * 2;
                float a0 = ah[l], a1 = ah[l + 1];
                float d0 = dh[l], d1 = dh[l + 1];
                s0 += acc[mf][nf][0] * a0 + acc[mf][nf][1] * a1;
                s1 += acc[mf][nf][2] * a0 + acc[mf][nf][3] * a1;
                t0 += acc[mf][nf][0] * d0 + acc[mf][nf][1] * d1;
                t1 += acc[mf][nf][2] * d0 + acc[mf][nf][3] * d1;
            }
            ps[mf][0][0] = s0; ps[mf][1][0] = s1;
            ps[mf][0][1] = t0; ps[mf][1][1] = t1;
        }
#pragma unroll
        for (int mf = 0; mf < 2; mf++)
#pragma unroll
            for (int hf = 0; hf < 2; hf++)
#pragma unroll
                for (int q = 0; q < 2; q++) {
                    ps[mf][hf][q] += __shfl_xor_sync(0xFFFFFFFF, ps[mf][hf][q], 1);
                    ps[mf][hf][q] += __shfl_xor_sync(0xFFFFFFFF, ps[mf][hf][q], 2);
                }
        if (tig == 0 && wn == 0) {
#pragma unroll
            for (int mf = 0; mf < 2; mf++)
#pragma unroll
                for (int hf = 0; hf < 2; hf++) {
                    int rl = (wm * 2 + mf) * 16 + hf * 8 + gid;
                    sred[rl * 2 + 0] = ps[mf][hf][0];
                    sred[rl * 2 + 1] = ps[mf][hf][1];
                }
        }
        __syncthreads();
        if (tig == 0 && wn == 1) {
#pragma unroll
            for (int mf = 0; mf < 2; mf++)
#pragma unroll
                for (int hf = 0; hf < 2; hf++) {
                    int rl = (wm * 2 + mf) * 16 + hf * 8 + gid;
                    int row = rowBase + rl;
                    if (row < M) {
                        als[row * H + hd] = ps[mf][hf][0] + sred[rl * 2 + 0];
                        ald[row * H + hd] = ps[mf][hf][1] + sred[rl * 2 + 1];
                    }
                }
        }
    }
}

// ---------------------------------------------------------------------------
// Init: zero degree histogram + pooling accumulators (one launch).
// ---------------------------------------------------------------------------
__global__ void init_kernel(int N)
{
    int i = blockIdx.x * blockDim.x + threadIdx.x;
    if (i < N) g_deg[i] = 0;
    if (i < 64 * 64) g_pool[i] = 0.f;
    if (i < 64) g_cnt[i] = 0.f;
}

__global__ void csr_hist_kernel(const int* __restrict__ ei, int E)
{
    int e = blockIdx.x * blockDim.x + threadIdx.x;
    if (e < E) atomicAdd(&g_deg[ei[E + e]], 1);
}

// Single-block exclusive scan (warp shuffle + cross-warp), N up to MAXN.
__global__ __launch_bounds__(1024) void csr_scan_kernel(int N)
{
    __shared__ int wsum[32];
    __shared__ int carry;
    int tid = threadIdx.x;
    int lane = tid & 31, w = tid >> 5;
    if (tid == 0) { carry = 0; g_rowptr[0] = 0; }
    __syncthreads();
    for (int base = 0; base < N; base += 1024) {
        int i = base + tid;
        int v = (i < N) ? g_deg[i] : 0;
        int x = v;
#pragma unroll
        for (int off = 1; off < 32; off <<= 1) {
            int t = __shfl_up_sync(0xFFFFFFFF, x, off);
            if (lane >= off) x += t;
        }
        if (lane == 31) wsum[w] = x;
        __syncthreads();
        if (w == 0) {
            int s = wsum[lane];
#pragma unroll
            for (int off = 1; off < 32; off <<= 1) {
                int t = __shfl_up_sync(0xFFFFFFFF, s, off);
                if (lane >= off) s += t;
            }
            wsum[lane] = s;
        }
        __syncthreads();
        int incl = x + (w > 0 ? wsum[w - 1] : 0);
        int c = carry;
        if (i < N) {
            g_rowptr[i + 1] = c + incl;
            g_cursor[i] = c + incl - v;
        }
        __syncthreads();
        if (tid == 1023) carry = c + incl;
        __syncthreads();
    }
}

__global__ void csr_fill_kernel(const int* __restrict__ ei, int E)
{
    int e = blockIdx.x * blockDim.x + threadIdx.x;
    if (e >= E) return;
    int s = ei[e], d = ei[E + e];
    int p = atomicAdd(&g_cursor[d], 1);
    g_col[p] = s;
    g_dst[p] = d;
}

// ---------------------------------------------------------------------------
// Edge exp: ex[p,h] = exp(leaky_relu(als[src]+ald[dst])) in CSR order.
// ---------------------------------------------------------------------------
__global__ void edge_ex4_kernel(int E, const float* __restrict__ als,
                                const float* __restrict__ ald)
{
    int p = blockIdx.x * blockDim.x + threadIdx.x;
    if (p >= E) return;
    int s = g_col[p], d = g_dst[p];
    float4 a = *(const float4*)&als[s * 4];
    float4 b = *(const float4*)&ald[d * 4];
    float4 v;
    v.x = a.x + b.x; v.x = (v.x > 0.f) ? v.x : 0.2f * v.x; v.x = __expf(v.x);
    v.y = a.y + b.y; v.y = (v.y > 0.f) ? v.y : 0.2f * v.y; v.y = __expf(v.y);
    v.z = a.z + b.z; v.z = (v.z > 0.f) ? v.z : 0.2f * v.z; v.z = __expf(v.z);
    v.w = a.w + b.w; v.w = (v.w > 0.f) ? v.w : 0.2f * v.w; v.w = __expf(v.w);
    *(float4*)&g_ex[(size_t)p * 4] = v;
}

__global__ void edge_ex1_kernel(int E, const float* __restrict__ als,
                                const float* __restrict__ ald)
{
    int p = blockIdx.x * blockDim.x + threadIdx.x;
    if (p >= E) return;
    float v = als[g_col[p]] + ald[g_dst[p]];
    v = (v > 0.f) ? v : 0.2f * v;
    g_ex[p] = __expf(v);
}

// ---------------------------------------------------------------------------
// Gather + softmax-normalize + bias + ELU (+ optional tf32-RNA rounding of the
// output when it feeds the next async GEMM). One dst per TPE threads.
// ---------------------------------------------------------------------------
template <int H, int C, bool ROUND>
__global__ __launch_bounds__(256) void gather_kernel(
    int N, const float* __restrict__ h,
    const float* __restrict__ als, const float* __restrict__ ald,
    const float* __restrict__ bias, float* __restrict__ out)
{
    constexpr int HC = H * C;
    constexpr int TPE = HC / 4;
    constexpr int DPB = 256 / TPE;
    int d = blockIdx.x * DPB + threadIdx.x / TPE;
    if (d >= N) return;
    int t = threadIdx.x % TPE;
    int hd = t / (C / 4);

    // self-loop
    float l = als[d * H + hd] + ald[d * H + hd];
    l = (l > 0.f) ? l : 0.2f * l;
    float exs = __expf(l);
    float4 hv = *(const float4*)(h + (size_t)d * HC + t * 4);
    float4 acc = make_float4(exs * hv.x, exs * hv.y, exs * hv.z, exs * hv.w);
    float den = exs;

    int p = g_rowptr[d], pend = g_rowptr[d + 1];
#pragma unroll 2
    for (; p < pend; p++) {
        int s = g_col[p];
        float ex = g_ex[(size_t)p * H + hd];
        float4 v = *(const float4*)(h + (size_t)s * HC + t * 4);
        acc.x += ex * v.x; acc.y += ex * v.y;
        acc.z += ex * v.z; acc.w += ex * v.w;
        den += ex;
    }
    float inv = 1.f / (den + 1e-16f);
    float4 bv = *(const float4*)(bias + t * 4);
    float4 o;
    o.x = acc.x * inv + bv.x; o.x = (o.x > 0.f) ? o.x : expm1f(o.x);
    o.y = acc.y * inv + bv.y; o.y = (o.y > 0.f) ? o.y : expm1f(o.y);
    o.z = acc.z * inv + bv.z; o.z = (o.z > 0.f) ? o.z : expm1f(o.z);
    o.w = acc.w * inv + bv.w; o.w = (o.w > 0.f) ? o.w : expm1f(o.w);
    if (ROUND) {
        o.x = __uint_as_float(f2tf32(o.x));
        o.y = __uint_as_float(f2tf32(o.y));
        o.z = __uint_as_float(f2tf32(o.z));
        o.w = __uint_as_float(f2tf32(o.w));
    }
    *(float4*)(out + (size_t)d * HC + t * 4) = o;
}

// ---------------------------------------------------------------------------
// Pooling (batch is sorted): run-length local accumulate, rare atomic flush.
// ---------------------------------------------------------------------------
__global__ __launch_bounds__(256) void pool_acc_kernel(
    const float* __restrict__ h, const int* __restrict__ batch, int N)
{
    int c = threadIdx.x & 63;
    int lane = threadIdx.x >> 6;
    int n0 = blockIdx.x * 64 + lane * 16;
    float acc = 0.f;
    int curg = -1, cnt = 0;
    for (int k = 0; k < 16; k++) {
        int n = n0 + k;
        if (n >= N) break;
        int g = batch[n];
        if (g != curg) {
            if (curg >= 0) {
                atomicAdd(&g_pool[curg * 64 + c], acc);
                if (c == 0) atomicAdd(&g_cnt[curg], (float)cnt);
            }
            curg = g; acc = 0.f; cnt = 0;
        }
        acc += h[(size_t)n * 64 + c];
        cnt++;
    }
    if (curg >= 0) {
        atomicAdd(&g_pool[curg * 64 + c], acc);
        if (c == 0) atomicAdd(&g_cnt[curg], (float)cnt);
    }
}

__global__ void final_linear_kernel(const float* __restrict__ linW,
                                    const float* __restrict__ linb,
                                    float* __restrict__ out)
{
    int idx = blockIdx.x * blockDim.x + threadIdx.x;
    if (idx >= 64 * 10) return;
    int g = idx / 10, o = idx % 10;
    float inv = 1.f / fmaxf(g_cnt[g], 1.f);
    float s = 0.f;
#pragma unroll 8
    for (int k = 0; k < 64; k++)
        s += g_pool[g * 64 + k] * inv * linW[k * 10 + o];
    out[idx] = s + linb[o];
}

// ---------------------------------------------------------------------------
// Host orchestration. Layer-1 GEMM is user launch #4 (the ncu-profiled one).
// ---------------------------------------------------------------------------
extern "C" void kernel_launch(void* const* d_in, const int* in_sizes, int n_in,
                              void* d_out, int out_size)
{
    const float* x     = (const float*)d_in[0];
    const int*   ei    = (const int*)d_in[1];
    const int*   batch = (const int*)d_in[2];
    const float* W1 = (const float*)d_in[3];   const float* b1 = (const float*)d_in[4];
    const float* as1 = (const float*)d_in[5];  const float* ad1 = (const float*)d_in[6];
    const float* W2 = (const float*)d_in[7];   const float* b2 = (const float*)d_in[8];
    const float* as2 = (const float*)d_in[9];  const float* ad2 = (const float*)d_in[10];
    const float* W3 = (const float*)d_in[11];  const float* b3 = (const float*)d_in[12];
    const float* as3 = (const float*)d_in[13]; const float* ad3 = (const float*)d_in[14];
    const float* linW = (const float*)d_in[15]; const float* linb = (const float*)d_in[16];
    float* out = (float*)d_out;

    int N = in_sizes[0] / 128;
    int E = in_sizes[1] / 2;

    float *hA, *hB, *als, *ald, *xc, *Wc;
    cudaGetSymbolAddress((void**)&hA,  g_hA);
    cudaGetSymbolAddress((void**)&hB,  g_hB);
    cudaGetSymbolAddress((void**)&als, g_als);
    cudaGetSymbolAddress((void**)&ald, g_ald);
    cudaGetSymbolAddress((void**)&xc,  g_xc);
    cudaGetSymbolAddress((void**)&Wc,  g_Wc);

    int gemmRows = (N + 127) / 128;

    // 1-3: conversions + init
    convert_x_kernel<<<(N * 32 + 255) / 256, 256>>>(x, xc, N * 32);  // N*128/4
    convert_w_kernel<<<(28672 + 255) / 256, 256>>>(W1, W2, W3);
    init_kernel<<<(N + 255) / 256, 256>>>(N);

    // 4: layer-1 GEMM (+ fused attn coefs)   <-- profiled launch
    tf32_gemm_kernel<<<dim3(4, gemmRows), 256>>>(xc, Wc, hA, N, 256, 128,
                                                 as1, ad1, als, ald, 4);
    // 5-7: CSR build
    csr_hist_kernel<<<(E + 255) / 256, 256>>>(ei, E);
    csr_scan_kernel<<<1, 1024>>>(N);
    csr_fill_kernel<<<(E + 255) / 256, 256>>>(ei, E);

    // Layer 1 edge phase (output rounded: feeds GEMM2)
    edge_ex4_kernel<<<(E + 255) / 256, 256>>>(E, als, ald);
    gather_kernel<4, 64, true><<<(N + 3) / 4, 256>>>(N, hA, als, ald, b1, hB);

    // Layer 2
    tf32_gemm_kernel<<<dim3(4, gemmRows), 256>>>(hB, Wc + 32768, hA, N, 256, 256,
                                                 as2, ad2, als, ald, 4);
    edge_ex4_kernel<<<(E + 255) / 256, 256>>>(E, als, ald);
    gather_kernel<4, 64, true><<<(N + 3) / 4, 256>>>(N, hA, als, ald, b2, hB);

    // Layer 3 (gather output unrounded: feeds pooling)
    tf32_gemm_kernel<<<dim3(1, gemmRows), 256>>>(hB, Wc + 98304, hA, N, 64, 256,
                                                 as3, ad3, als, ald, 1);
    edge_ex1_kernel<<<(E + 255) / 256, 256>>>(E, als, ald);
    gather_kernel<1, 64, false><<<(N + 15) / 16, 256>>>(N, hA, als, ald, b3, hB);

    // Pool + final linear
    pool_acc_kernel<<<(N + 63) / 64, 256>>>(hB, batch, N);
    final_linear_kernel<<<3, 256>>>(linW, linb, out);
}

// round 8
// speedup vs baseline: 3.7136x; 1.1035x over previous
#include <cuda_runtime.h>
#include <cuda_fp16.h>
#include <math.h>
#include <stdint.h>

// ---------------------------------------------------------------------------
// Problem constants: N=50000, E=600000, IN=128, HID=64, HEADS=4, OUT=10, G=64
// ---------------------------------------------------------------------------
#define MAXN 50048
#define MAXE 600064

// Scratch (device globals — no allocations allowed)
__device__ __align__(16) __half g_hH[(size_t)MAXN * 256];  // GEMM output h (fp16)
__device__ __align__(16) float g_hB[(size_t)MAXN * 256];   // layer activations
__device__ __align__(16) float g_xc[(size_t)MAXN * 128];   // tf32-rounded x
__device__ __align__(16) float g_Wc[114688];               // tf32-rounded W1|W2|W3
__device__ __align__(16) float g_ex[(size_t)MAXE * 4];     // CSR-ordered exp(logit)
__device__ __align__(16) float g_als[(size_t)MAXN * 4];    // alpha_src coeffs
__device__ __align__(16) float g_ald[(size_t)MAXN * 4];    // alpha_dst coeffs
__device__ int g_deg[MAXN];
__device__ int g_rowptr[MAXN + 1];
__device__ int g_cursor[MAXN];
__device__ int g_col[MAXE];        // src per CSR slot
__device__ int g_dst[MAXE];        // dst per CSR slot
__device__ __align__(16) float g_pool[64 * 64];
__device__ __align__(16) float g_cnt[64];

__device__ __forceinline__ uint32_t f2tf32(float x)
{
    uint32_t r;
    asm("cvt.rna.tf32.f32 %0, %1;" : "=r"(r) : "f"(x));
    return r;
}

// ---------------------------------------------------------------------------
// tf32-RNA rounding pre-passes (cp.async copies raw bits; rounding hoisted).
// ---------------------------------------------------------------------------
__global__ void convert_x_kernel(const float* __restrict__ in,
                                 float* __restrict__ out, int n4)
{
    int i = blockIdx.x * blockDim.x + threadIdx.x;
    if (i >= n4) return;
    float4 v = ((const float4*)in)[i];
    float4 o;
    o.x = __uint_as_float(f2tf32(v.x));
    o.y = __uint_as_float(f2tf32(v.y));
    o.z = __uint_as_float(f2tf32(v.z));
    o.w = __uint_as_float(f2tf32(v.w));
    ((float4*)out)[i] = o;
}

// W1 (128x256) -> [0:32768), W2 (256x256) -> [32768:98304), W3 (256x64) -> [98304:114688)
__global__ void convert_w_kernel(const float* __restrict__ W1,
                                 const float* __restrict__ W2,
                                 const float* __restrict__ W3)
{
    int i = blockIdx.x * blockDim.x + threadIdx.x;   // float4 index, 28672 total
    if (i >= 28672) return;
    const float* src;
    int j;
    if (i < 8192)       { src = W1; j = i; }
    else if (i < 24576) { src = W2; j = i - 8192; }
    else                { src = W3; j = i - 24576; }
    float4 v = ((const float4*)src)[j];
    float4 o;
    o.x = __uint_as_float(f2tf32(v.x));
    o.y = __uint_as_float(f2tf32(v.y));
    o.z = __uint_as_float(f2tf32(v.z));
    o.w = __uint_as_float(f2tf32(v.w));
    ((float4*)g_Wc)[i] = o;
}

// ---------------------------------------------------------------------------
// TF32 tensor-core GEMM, cp.async 2-stage pipeline, fused attn-coef epilogue.
// Output h is stored ONLY as fp16 (tf32 and fp16 share a 10-bit mantissa, so
// downstream consumers lose nothing). Inputs must be tf32-RNA-pre-rounded.
// BM=128, BN=64(=one head), BK=32. 8 warps; warp tile 32x32.
// ---------------------------------------------------------------------------
__global__ __launch_bounds__(256, 3) void tf32_gemm_kernel(
    const float* __restrict__ A, const float* __restrict__ B,
    __half* __restrict__ Ch, int M, int N, int K,
    const float* __restrict__ asrc, const float* __restrict__ adst,
    float* __restrict__ als, float* __restrict__ ald, int H)
{
    __shared__ uint32_t As[2][4096];   // 128 x 32, swizzled
    __shared__ uint32_t Bs[2][2048];   // 32 x 64, swizzled

    int tid = threadIdx.x;
    int warp = tid >> 5, lane = tid & 31;
    int gid = lane >> 2, tig = lane & 3;
    int wm = warp & 3, wn = warp >> 2;           // wm 0..3 (M), wn 0..1 (N)
    int rowBase = blockIdx.y * 128;
    int colBase = blockIdx.x * 64;

    uint32_t asBase, bsBase;
    {
        asm("{ .reg .u64 t; cvta.to.shared.u64 t, %1; cvt.u32.u64 %0, t; }"
            : "=r"(asBase) : "l"(&As[0][0]));
        asm("{ .reg .u64 t; cvta.to.shared.u64 t, %1; cvt.u32.u64 %0, t; }"
            : "=r"(bsBase) : "l"(&Bs[0][0]));
    }

    float acc[2][4][4];
#pragma unroll
    for (int i = 0; i < 2; i++)
#pragma unroll
        for (int j = 0; j < 4; j++)
#pragma unroll
            for (int r = 0; r < 4; r++) acc[i][j][r] = 0.f;

    auto issue = [&](int k0, int buf) {
#pragma unroll
        for (int i = 0; i < 4; i++) {
            int f = tid + i * 256;
            int m = f >> 3, kb = (f & 7) * 4;
            uint32_t off = m * 32 + (kb ^ ((m & 7) * 4));
            int gr = rowBase + m;
            const float* src = A + (size_t)(gr < M ? gr : M - 1) * K + k0 + kb;
            int sz = (gr < M) ? 16 : 0;
            uint32_t dst = asBase + (buf * 4096 + off) * 4;
            asm volatile("cp.async.cg.shared.global [%0], [%1], 16, %2;"
                         :: "r"(dst), "l"(src), "r"(sz));
        }
#pragma unroll
        for (int i = 0; i < 2; i++) {
            int f = tid + i * 256;
            int k = f >> 4, nb = (f & 15) * 4;
            uint32_t off = k * 64 + (nb ^ ((k & 3) * 8));
            const float* src = B + (size_t)(k0 + k) * N + colBase + nb;
            uint32_t dst = bsBase + (buf * 2048 + off) * 4;
            asm volatile("cp.async.cg.shared.global [%0], [%1], 16;"
                         :: "r"(dst), "l"(src));
        }
        asm volatile("cp.async.commit_group;");
    };

    auto compute = [&](int buf) {
        const uint32_t* Ab = &As[buf][0];
        const uint32_t* Bb = &Bs[buf][0];
        int swA = gid * 4;
        int swB = tig * 8;
#pragma unroll
        for (int ks = 0; ks < 4; ks++) {
            uint32_t a[2][4];
            uint32_t b[4][2];
            int k0 = ks * 8 + tig;
#pragma unroll
            for (int mf = 0; mf < 2; mf++) {
                int row = (wm * 2 + mf) * 16 + gid;
                const uint32_t* r0 = Ab + row * 32;
                a[mf][0] = r0[k0 ^ swA];
                a[mf][1] = r0[256 + (k0 ^ swA)];          // +8 rows
                a[mf][2] = r0[(k0 + 4) ^ swA];
                a[mf][3] = r0[256 + ((k0 + 4) ^ swA)];
            }
#pragma unroll
            for (int nf = 0; nf < 4; nf++) {
                int col = (wn * 4 + nf) * 8 + gid;
                b[nf][0] = Bb[(ks * 8 + tig) * 64 + (col ^ swB)];
                b[nf][1] = Bb[(ks * 8 + tig + 4) * 64 + (col ^ swB)];
            }
#pragma unroll
            for (int mf = 0; mf < 2; mf++)
#pragma unroll
                for (int nf = 0; nf < 4; nf++) {
                    asm volatile(
                        "mma.sync.aligned.m16n8k8.row.col.f32.tf32.tf32.f32 "
                        "{%0,%1,%2,%3},{%4,%5,%6,%7},{%8,%9},{%0,%1,%2,%3};"
                        : "+f"(acc[mf][nf][0]), "+f"(acc[mf][nf][1]),
                          "+f"(acc[mf][nf][2]), "+f"(acc[mf][nf][3])
                        : "r"(a[mf][0]), "r"(a[mf][1]), "r"(a[mf][2]), "r"(a[mf][3]),
                          "r"(b[nf][0]), "r"(b[nf][1]));
                }
        }
    };

    int nt = K >> 5;             // K/32 tiles
    issue(0, 0);
    int buf = 0;
    for (int t = 0; t < nt; t++) {
        if (t + 1 < nt) issue((t + 1) * 32, buf ^ 1);
        else            asm volatile("cp.async.commit_group;");
        asm volatile("cp.async.wait_group 1;");
        __syncthreads();
        compute(buf);
        __syncthreads();
        buf ^= 1;
    }

    // C store (fp16 only): c0/c1 at (row0, col..col+1); c2/c3 at row0+8.
#pragma unroll
    for (int mf = 0; mf < 2; mf++) {
        int row0 = rowBase + (wm * 2 + mf) * 16 + gid;
#pragma unroll
        for (int nf = 0; nf < 4; nf++) {
            int col = colBase + (wn * 4 + nf) * 8 + tig * 2;
            if (row0 < M)
                *(__half2*)(Ch + (size_t)row0 * N + col) =
                    __floats2half2_rn(acc[mf][nf][0], acc[mf][nf][1]);
            if (row0 + 8 < M)
                *(__half2*)(Ch + (size_t)(row0 + 8) * N + col) =
                    __floats2half2_rn(acc[mf][nf][2], acc[mf][nf][3]);
        }
    }

    // ---- fused attn-coef epilogue: als/ald row dots for this head ----
    {
        int hd = blockIdx.x;                       // BN == C == 64
        const float* ah = asrc + hd * 64;
        const float* dh = adst + hd * 64;
        float* sred = (float*)&As[0][0];           // post-loop: buffers free
        float ps[2][2][2];                         // [mf][half][src/dst]
#pragma unroll
        for (int mf = 0; mf < 2; mf++) {
            float s0 = 0.f, s1 = 0.f, t0 = 0.f, t1 = 0.f;
#pragma unroll
            for (int nf = 0; nf < 4; nf++) {
                int l = (wn * 4 + nf) * 8 + tig * 2;
                float a0 = ah[l], a1 = ah[l + 1];
                float d0 = dh[l], d1 = dh[l + 1];
                s0 += acc[mf][nf][0] * a0 + acc[mf][nf][1] * a1;
                s1 += acc[mf][nf][2] * a0 + acc[mf][nf][3] * a1;
                t0 += acc[mf][nf][0] * d0 + acc[mf][nf][1] * d1;
                t1 += acc[mf][nf][2] * d0 + acc[mf][nf][3] * d1;
            }
            ps[mf][0][0] = s0; ps[mf][1][0] = s1;
            ps[mf][0][1] = t0; ps[mf][1][1] = t1;
        }
#pragma unroll
        for (int mf = 0; mf < 2; mf++)
#pragma unroll
            for (int hf = 0; hf < 2; hf++)
#pragma unroll
                for (int q = 0; q < 2; q++) {
                    ps[mf][hf][q] += __shfl_xor_sync(0xFFFFFFFF, ps[mf][hf][q], 1);
                    ps[mf][hf][q] += __shfl_xor_sync(0xFFFFFFFF, ps[mf][hf][q], 2);
                }
        if (tig == 0 && wn == 0) {
#pragma unroll
            for (int mf = 0; mf < 2; mf++)
#pragma unroll
                for (int hf = 0; hf < 2; hf++) {
                    int rl = (wm * 2 + mf) * 16 + hf * 8 + gid;
                    sred[rl * 2 + 0] = ps[mf][hf][0];
                    sred[rl * 2 + 1] = ps[mf][hf][1];
                }
        }
        __syncthreads();
        if (tig == 0 && wn == 1) {
#pragma unroll
            for (int mf = 0; mf < 2; mf++)
#pragma unroll
                for (int hf = 0; hf < 2; hf++) {
                    int rl = (wm * 2 + mf) * 16 + hf * 8 + gid;
                    int row = rowBase + rl;
                    if (row < M) {
                        als[row * H + hd] = ps[mf][hf][0] + sred[rl * 2 + 0];
                        ald[row * H + hd] = ps[mf][hf][1] + sred[rl * 2 + 1];
                    }
                }
        }
    }
}

// ---------------------------------------------------------------------------
// Init: zero degree histogram + pooling accumulators (one launch).
// ---------------------------------------------------------------------------
__global__ void init_kernel(int N)
{
    int i = blockIdx.x * blockDim.x + threadIdx.x;
    if (i < N) g_deg[i] = 0;
    if (i < 64 * 64) g_pool[i] = 0.f;
    if (i < 64) g_cnt[i] = 0.f;
}

__global__ void csr_hist_kernel(const int* __restrict__ ei, int E)
{
    int e = blockIdx.x * blockDim.x + threadIdx.x;
    if (e < E) atomicAdd(&g_deg[ei[E + e]], 1);
}

// Single-block exclusive scan (warp shuffle + cross-warp), N up to MAXN.
__global__ __launch_bounds__(1024) void csr_scan_kernel(int N)
{
    __shared__ int wsum[32];
    __shared__ int carry;
    int tid = threadIdx.x;
    int lane = tid & 31, w = tid >> 5;
    if (tid == 0) { carry = 0; g_rowptr[0] = 0; }
    __syncthreads();
    for (int base = 0; base < N; base += 1024) {
        int i = base + tid;
        int v = (i < N) ? g_deg[i] : 0;
        int x = v;
#pragma unroll
        for (int off = 1; off < 32; off <<= 1) {
            int t = __shfl_up_sync(0xFFFFFFFF, x, off);
            if (lane >= off) x += t;
        }
        if (lane == 31) wsum[w] = x;
        __syncthreads();
        if (w == 0) {
            int s = wsum[lane];
#pragma unroll
            for (int off = 1; off < 32; off <<= 1) {
                int t = __shfl_up_sync(0xFFFFFFFF, s, off);
                if (lane >= off) s += t;
            }
            wsum[lane] = s;
        }
        __syncthreads();
        int incl = x + (w > 0 ? wsum[w - 1] : 0);
        int c = carry;
        if (i < N) {
            g_rowptr[i + 1] = c + incl;
            g_cursor[i] = c + incl - v;
        }
        __syncthreads();
        if (tid == 1023) carry = c + incl;
        __syncthreads();
    }
}

__global__ void csr_fill_kernel(const int* __restrict__ ei, int E)
{
    int e = blockIdx.x * blockDim.x + threadIdx.x;
    if (e >= E) return;
    int s = ei[e], d = ei[E + e];
    int p = atomicAdd(&g_cursor[d], 1);
    g_col[p] = s;
    g_dst[p] = d;
}

// ---------------------------------------------------------------------------
// Edge exp: ex[p,h] = exp(leaky_relu(als[src]+ald[dst])) in CSR order.
// ---------------------------------------------------------------------------
__global__ void edge_ex4_kernel(int E, const float* __restrict__ als,
                                const float* __restrict__ ald)
{
    int p = blockIdx.x * blockDim.x + threadIdx.x;
    if (p >= E) return;
    int s = g_col[p], d = g_dst[p];
    float4 a = *(const float4*)&als[s * 4];
    float4 b = *(const float4*)&ald[d * 4];
    float4 v;
    v.x = a.x + b.x; v.x = (v.x > 0.f) ? v.x : 0.2f * v.x; v.x = __expf(v.x);
    v.y = a.y + b.y; v.y = (v.y > 0.f) ? v.y : 0.2f * v.y; v.y = __expf(v.y);
    v.z = a.z + b.z; v.z = (v.z > 0.f) ? v.z : 0.2f * v.z; v.z = __expf(v.z);
    v.w = a.w + b.w; v.w = (v.w > 0.f) ? v.w : 0.2f * v.w; v.w = __expf(v.w);
    *(float4*)&g_ex[(size_t)p * 4] = v;
}

__global__ void edge_ex1_kernel(int E, const float* __restrict__ als,
                                const float* __restrict__ ald)
{
    int p = blockIdx.x * blockDim.x + threadIdx.x;
    if (p >= E) return;
    float v = als[g_col[p]] + ald[g_dst[p]];
    v = (v > 0.f) ? v : 0.2f * v;
    g_ex[p] = __expf(v);
}

// ---------------------------------------------------------------------------
// Gather (fp16 messages) + softmax-normalize + bias + ELU (+ optional tf32
// rounding). TPE = HC/8 threads per dst; each thread covers 8 channels of one
// head via a single uint4 (8 halves) load per edge.
// ---------------------------------------------------------------------------
__device__ __forceinline__ void unpack8(uint4 r, float* v)
{
    float2 p;
    p = __half22float2(*(__half2*)&r.x); v[0] = p.x; v[1] = p.y;
    p = __half22float2(*((__half2*)&r.x + 1)); v[2] = p.x; v[3] = p.y;
    p = __half22float2(*(__half2*)&r.z); v[4] = p.x; v[5] = p.y;
    p = __half22float2(*((__half2*)&r.z + 1)); v[6] = p.x; v[7] = p.y;
}

template <int H, int C, bool ROUND>
__global__ __launch_bounds__(256) void gather_kernel(
    int N, const __half* __restrict__ h,
    const float* __restrict__ als, const float* __restrict__ ald,
    const float* __restrict__ bias, float* __restrict__ out)
{
    constexpr int HC = H * C;
    constexpr int TPE = HC / 8;
    constexpr int DPB = 256 / TPE;
    int d = blockIdx.x * DPB + threadIdx.x / TPE;
    if (d >= N) return;
    int t = threadIdx.x % TPE;
    int hd = t / (C / 8);

    // self-loop
    float l = als[d * H + hd] + ald[d * H + hd];
    l = (l > 0.f) ? l : 0.2f * l;
    float exs = __expf(l);
    float den = exs;
    float acc[8], v[8];
    uint4 raw = *(const uint4*)(h + (size_t)d * HC + t * 8);
    unpack8(raw, v);
#pragma unroll
    for (int i = 0; i < 8; i++) acc[i] = exs * v[i];

    int p = g_rowptr[d], pend = g_rowptr[d + 1];
    for (; p < pend; p++) {
        int s = g_col[p];
        float ex = g_ex[(size_t)p * H + hd];
        raw = *(const uint4*)(h + (size_t)s * HC + t * 8);
        unpack8(raw, v);
#pragma unroll
        for (int i = 0; i < 8; i++) acc[i] += ex * v[i];
        den += ex;
    }
    float inv = 1.f / (den + 1e-16f);
    float4 bv0 = *(const float4*)(bias + t * 8);
    float4 bv1 = *(const float4*)(bias + t * 8 + 4);
    float o[8];
    float bb[8] = {bv0.x, bv0.y, bv0.z, bv0.w, bv1.x, bv1.y, bv1.z, bv1.w};
#pragma unroll
    for (int i = 0; i < 8; i++) {
        float x = acc[i] * inv + bb[i];
        x = (x > 0.f) ? x : expm1f(x);
        if (ROUND) x = __uint_as_float(f2tf32(x));
        o[i] = x;
    }
    float* op = out + (size_t)d * HC + t * 8;
    *(float4*)op = make_float4(o[0], o[1], o[2], o[3]);
    *(float4*)(op + 4) = make_float4(o[4], o[5], o[6], o[7]);
}

// ---------------------------------------------------------------------------
// Pooling (batch is sorted): run-length local accumulate, rare atomic flush.
// ---------------------------------------------------------------------------
__global__ __launch_bounds__(256) void pool_acc_kernel(
    const float* __restrict__ h, const int* __restrict__ batch, int N)
{
    int c = threadIdx.x & 63;
    int lane = threadIdx.x >> 6;
    int n0 = blockIdx.x * 64 + lane * 16;
    float acc = 0.f;
    int curg = -1, cnt = 0;
    for (int k = 0; k < 16; k++) {
        int n = n0 + k;
        if (n >= N) break;
        int g = batch[n];
        if (g != curg) {
            if (curg >= 0) {
                atomicAdd(&g_pool[curg * 64 + c], acc);
                if (c == 0) atomicAdd(&g_cnt[curg], (float)cnt);
            }
            curg = g; acc = 0.f; cnt = 0;
        }
        acc += h[(size_t)n * 64 + c];
        cnt++;
    }
    if (curg >= 0) {
        atomicAdd(&g_pool[curg * 64 + c], acc);
        if (c == 0) atomicAdd(&g_cnt[curg], (float)cnt);
    }
}

__global__ void final_linear_kernel(const float* __restrict__ linW,
                                    const float* __restrict__ linb,
                                    float* __restrict__ out)
{
    int idx = blockIdx.x * blockDim.x + threadIdx.x;
    if (idx >= 64 * 10) return;
    int g = idx / 10, o = idx % 10;
    float inv = 1.f / fmaxf(g_cnt[g], 1.f);
    float s = 0.f;
#pragma unroll 8
    for (int k = 0; k < 64; k++)
        s += g_pool[g * 64 + k] * inv * linW[k * 10 + o];
    out[idx] = s + linb[o];
}

// ---------------------------------------------------------------------------
// Host orchestration. Layer-1 GEMM is user launch #4 (the ncu-profiled one).
// ---------------------------------------------------------------------------
extern "C" void kernel_launch(void* const* d_in, const int* in_sizes, int n_in,
                              void* d_out, int out_size)
{
    const float* x     = (const float*)d_in[0];
    const int*   ei    = (const int*)d_in[1];
    const int*   batch = (const int*)d_in[2];
    const float* W1 = (const float*)d_in[3];   const float* b1 = (const float*)d_in[4];
    const float* as1 = (const float*)d_in[5];  const float* ad1 = (const float*)d_in[6];
    const float* W2 = (const float*)d_in[7];   const float* b2 = (const float*)d_in[8];
    const float* as2 = (const float*)d_in[9];  const float* ad2 = (const float*)d_in[10];
    const float* W3 = (const float*)d_in[11];  const float* b3 = (const float*)d_in[12];
    const float* as3 = (const float*)d_in[13]; const float* ad3 = (const float*)d_in[14];
    const float* linW = (const float*)d_in[15]; const float* linb = (const float*)d_in[16];
    float* out = (float*)d_out;

    int N = in_sizes[0] / 128;
    int E = in_sizes[1] / 2;

    float *hB, *als, *ald, *xc, *Wc;
    __half *hH;
    cudaGetSymbolAddress((void**)&hH,  g_hH);
    cudaGetSymbolAddress((void**)&hB,  g_hB);
    cudaGetSymbolAddress((void**)&als, g_als);
    cudaGetSymbolAddress((void**)&ald, g_ald);
    cudaGetSymbolAddress((void**)&xc,  g_xc);
    cudaGetSymbolAddress((void**)&Wc,  g_Wc);

    int gemmRows = (N + 127) / 128;

    // 1-3: conversions + init
    convert_x_kernel<<<(N * 32 + 255) / 256, 256>>>(x, xc, N * 32);  // N*128/4
    convert_w_kernel<<<(28672 + 255) / 256, 256>>>(W1, W2, W3);
    init_kernel<<<(N + 255) / 256, 256>>>(N);

    // 4: layer-1 GEMM (+ fused attn coefs)   <-- profiled launch
    tf32_gemm_kernel<<<dim3(4, gemmRows), 256>>>(xc, Wc, hH, N, 256, 128,
                                                 as1, ad1, als, ald, 4);
    // 5-7: CSR build
    csr_hist_kernel<<<(E + 255) / 256, 256>>>(ei, E);
    csr_scan_kernel<<<1, 1024>>>(N);
    csr_fill_kernel<<<(E + 255) / 256, 256>>>(ei, E);

    // Layer 1 edge phase (output rounded: feeds GEMM2)
    edge_ex4_kernel<<<(E + 255) / 256, 256>>>(E, als, ald);
    gather_kernel<4, 64, true><<<(N + 7) / 8, 256>>>(N, hH, als, ald, b1, hB);

    // Layer 2
    tf32_gemm_kernel<<<dim3(4, gemmRows), 256>>>(hB, Wc + 32768, hH, N, 256, 256,
                                                 as2, ad2, als, ald, 4);
    edge_ex4_kernel<<<(E + 255) / 256, 256>>>(E, als, ald);
    gather_kernel<4, 64, true><<<(N + 7) / 8, 256>>>(N, hH, als, ald, b2, hB);

    // Layer 3 (gather output unrounded: feeds pooling)
    tf32_gemm_kernel<<<dim3(1, gemmRows), 256>>>(hB, Wc + 98304, hH, N, 64, 256,
                                                 as3, ad3, als, ald, 1);
    edge_ex1_kernel<<<(E + 255) / 256, 256>>>(E, als, ald);
    gather_kernel<1, 64, false><<<(N + 31) / 32, 256>>>(N, hH, als, ald, b3, hB);

    // Pool + final linear
    pool_acc_kernel<<<(N + 63) / 64, 256>>>(hB, batch, N);
    final_linear_kernel<<<3, 256>>>(linW, linb, out);
}

// round 9
// speedup vs baseline: 4.3308x; 1.1662x over previous
#include <cuda_runtime.h>
#include <cuda_fp16.h>
#include <math.h>
#include <stdint.h>

// ---------------------------------------------------------------------------
// Problem constants: N=50000, E=600000, IN=128, HID=64, HEADS=4, OUT=10, G=64
// ---------------------------------------------------------------------------
#define MAXN 50048
#define MAXE 600064

// Scratch (device globals — no allocations allowed)
__device__ __align__(16) __half g_hH[(size_t)MAXN * 256];  // GEMM output h (fp16)
__device__ __align__(16) __half g_hG[(size_t)MAXN * 256];  // gather out L1/L2 (fp16)
__device__ __align__(16) float  g_hB3[(size_t)MAXN * 64];  // gather out L3 (fp32)
__device__ __align__(16) __half g_xh[(size_t)MAXN * 128];  // fp16 x
__device__ __align__(16) __half g_Wh[114688];              // fp16 W1^T|W2^T|W3^T  [N][K]
__device__ __align__(16) float g_ex[(size_t)MAXE * 4];     // CSR-ordered exp(logit)
__device__ __align__(16) float g_als[(size_t)MAXN * 4];    // alpha_src coeffs
__device__ __align__(16) float g_ald[(size_t)MAXN * 4];    // alpha_dst coeffs
__device__ int g_deg[MAXN];
__device__ int g_rowptr[MAXN + 1];
__device__ int g_cursor[MAXN];
__device__ int g_col[MAXE];        // src per CSR slot
__device__ int g_dst[MAXE];        // dst per CSR slot
__device__ __align__(16) float g_pool[64 * 64];
__device__ __align__(16) float g_cnt[64];

// ---------------------------------------------------------------------------
// fp16 conversion pre-passes.
// ---------------------------------------------------------------------------
__global__ void convert_x_kernel(const float* __restrict__ in,
                                 __half* __restrict__ out, int n4)
{
    int i = blockIdx.x * blockDim.x + threadIdx.x;
    if (i >= n4) return;
    float4 v = ((const float4*)in)[i];
    __half2* o = (__half2*)out + i * 2;
    o[0] = __floats2half2_rn(v.x, v.y);
    o[1] = __floats2half2_rn(v.z, v.w);
}

// Transposed fp16 weights: Wt[n*K+k] = W[k*N+n].
// W1t (256x128) -> [0:32768), W2t (256x256) -> [32768:98304), W3t (64x256) -> [98304:114688)
__global__ void convert_wT_kernel(const float* __restrict__ W1,
                                  const float* __restrict__ W2,
                                  const float* __restrict__ W3)
{
    int j = blockIdx.x * blockDim.x + threadIdx.x;
    if (j >= 114688) return;
    const float* src;
    int jj, K, N;
    if (j < 32768)       { src = W1; jj = j;          K = 128; N = 256; }
    else if (j < 98304)  { src = W2; jj = j - 32768;  K = 256; N = 256; }
    else                 { src = W3; jj = j - 98304;  K = 256; N = 64;  }
    int n = jj / K, k = jj % K;
    g_Wh[j] = __float2half_rn(src[k * N + n]);
}

// ---------------------------------------------------------------------------
// fp16 tensor-core GEMM (m16n8k16, ldmatrix), cp.async 2-stage pipeline,
// fused attn-coef epilogue. A fp16 [M][K]; Bt fp16 [N][K] (transposed weight).
// BM=128, BN=64(=one head), BK=32. 8 warps; warp tile 32x32.
// Smem chunk swizzle: 16B chunk q at row r lives at q ^ ((r>>1)&3).
// ---------------------------------------------------------------------------
__global__ __launch_bounds__(256, 3) void h16_gemm_kernel(
    const __half* __restrict__ A, const __half* __restrict__ Bt,
    __half* __restrict__ Ch, int M, int N, int K,
    const float* __restrict__ asrc, const float* __restrict__ adst,
    float* __restrict__ als, float* __restrict__ ald, int H)
{
    __shared__ __align__(16) __half As[2][128 * 32];   // 8KB per buffer
    __shared__ __align__(16) __half Bs[2][64 * 32];    // 4KB per buffer

    int tid = threadIdx.x;
    int warp = tid >> 5, lane = tid & 31;
    int gid = lane >> 2, tig = lane & 3;
    int wm = warp & 3, wn = warp >> 2;           // wm 0..3 (M), wn 0..1 (N)
    int rowBase = blockIdx.y * 128;
    int colBase = blockIdx.x * 64;

    uint32_t asBase, bsBase;
    asm("{ .reg .u64 t; cvta.to.shared.u64 t, %1; cvt.u32.u64 %0, t; }"
        : "=r"(asBase) : "l"(&As[0][0]));
    asm("{ .reg .u64 t; cvta.to.shared.u64 t, %1; cvt.u32.u64 %0, t; }"
        : "=r"(bsBase) : "l"(&Bs[0][0]));

    float acc[2][4][4];
#pragma unroll
    for (int i = 0; i < 2; i++)
#pragma unroll
        for (int j = 0; j < 4; j++)
#pragma unroll
            for (int r = 0; r < 4; r++) acc[i][j][r] = 0.f;

    // A tile: 128 rows x 32 halves (64B = 4 chunks) -> 512 chunks, 2/thread.
    // B tile: 64 rows x 32 halves -> 256 chunks, 1/thread.
    auto issue = [&](int k0, int buf) {
#pragma unroll
        for (int i = 0; i < 2; i++) {
            int f = tid + i * 256;
            int m = f >> 2, q = f & 3;
            int qs = q ^ ((m >> 1) & 3);
            int gr = rowBase + m;
            const __half* src = A + (size_t)(gr < M ? gr : M - 1) * K + k0 + q * 8;
            int sz = (gr < M) ? 16 : 0;
            uint32_t dst = asBase + buf * 8192 + m * 64 + qs * 16;
            asm volatile("cp.async.cg.shared.global [%0], [%1], 16, %2;"
                         :: "r"(dst), "l"(src), "r"(sz));
        }
        {
            int n = tid >> 2, q = tid & 3;
            int qs = q ^ ((n >> 1) & 3);
            const __half* src = Bt + (size_t)(colBase + n) * K + k0 + q * 8;
            uint32_t dst = bsBase + buf * 4096 + n * 64 + qs * 16;
            asm volatile("cp.async.cg.shared.global [%0], [%1], 16;"
                         :: "r"(dst), "l"(src));
        }
        asm volatile("cp.async.commit_group;");
    };

    auto compute = [&](int buf) {
        uint32_t aB = asBase + buf * 8192;
        uint32_t bB = bsBase + buf * 4096;
        int lrow = lane & 15;
        int chHalf = lane >> 4;                     // which k8-chunk within kstep
#pragma unroll
        for (int ks = 0; ks < 2; ks++) {
            int ch = ks * 2 + chHalf;
            uint32_t a[2][4], b[2][4];
#pragma unroll
            for (int mf = 0; mf < 2; mf++) {
                int row = (wm * 2 + mf) * 16 + lrow;
                uint32_t addr = aB + row * 64 + ((ch ^ ((row >> 1) & 3)) * 16);
                asm volatile(
                    "ldmatrix.sync.aligned.m8n8.x4.shared.b16 {%0,%1,%2,%3}, [%4];"
                    : "=r"(a[mf][0]), "=r"(a[mf][1]), "=r"(a[mf][2]), "=r"(a[mf][3])
                    : "r"(addr));
            }
#pragma unroll
            for (int pr = 0; pr < 2; pr++) {
                int n = wn * 32 + pr * 16 + lrow;
                uint32_t addr = bB + n * 64 + ((ch ^ ((n >> 1) & 3)) * 16);
                asm volatile(
                    "ldmatrix.sync.aligned.m8n8.x4.shared.b16 {%0,%1,%2,%3}, [%4];"
                    : "=r"(b[pr][0]), "=r"(b[pr][1]), "=r"(b[pr][2]), "=r"(b[pr][3])
                    : "r"(addr));
            }
#pragma unroll
            for (int mf = 0; mf < 2; mf++)
#pragma unroll
                for (int nf = 0; nf < 4; nf++) {
                    int pr = nf >> 1, sub = nf & 1;
                    asm volatile(
                        "mma.sync.aligned.m16n8k16.row.col.f32.f16.f16.f32 "
                        "{%0,%1,%2,%3},{%4,%5,%6,%7},{%8,%9},{%0,%1,%2,%3};"
                        : "+f"(acc[mf][nf][0]), "+f"(acc[mf][nf][1]),
                          "+f"(acc[mf][nf][2]), "+f"(acc[mf][nf][3])
                        : "r"(a[mf][0]), "r"(a[mf][1]), "r"(a[mf][2]), "r"(a[mf][3]),
                          "r"(b[pr][sub]), "r"(b[pr][sub + 2]));
                }
        }
    };

    int nt = K >> 5;             // K/32 tiles
    issue(0, 0);
    int buf = 0;
    for (int t = 0; t < nt; t++) {
        if (t + 1 < nt) issue((t + 1) * 32, buf ^ 1);
        else            asm volatile("cp.async.commit_group;");
        asm volatile("cp.async.wait_group 1;");
        __syncthreads();
        compute(buf);
        __syncthreads();
        buf ^= 1;
    }

    // C store (fp16): c0/c1 at (row0, col..col+1); c2/c3 at row0+8.
#pragma unroll
    for (int mf = 0; mf < 2; mf++) {
        int row0 = rowBase + (wm * 2 + mf) * 16 + gid;
#pragma unroll
        for (int nf = 0; nf < 4; nf++) {
            int col = colBase + (wn * 4 + nf) * 8 + tig * 2;
            if (row0 < M)
                *(__half2*)(Ch + (size_t)row0 * N + col) =
                    __floats2half2_rn(acc[mf][nf][0], acc[mf][nf][1]);
            if (row0 + 8 < M)
                *(__half2*)(Ch + (size_t)(row0 + 8) * N + col) =
                    __floats2half2_rn(acc[mf][nf][2], acc[mf][nf][3]);
        }
    }

    // ---- fused attn-coef epilogue: als/ald row dots for this head ----
    {
        int hd = blockIdx.x;                       // BN == C == 64
        const float* ah = asrc + hd * 64;
        const float* dh = adst + hd * 64;
        float* sred = (float*)&As[0][0];           // post-loop: buffers free
        float ps[2][2][2];                         // [mf][half][src/dst]
#pragma unroll
        for (int mf = 0; mf < 2; mf++) {
            float s0 = 0.f, s1 = 0.f, t0 = 0.f, t1 = 0.f;
#pragma unroll
            for (int nf = 0; nf < 4; nf++) {
                int l = (wn * 4 + nf) * 8 + tig * 2;
                float a0 = ah[l], a1 = ah[l + 1];
                float d0 = dh[l], d1 = dh[l + 1];
                s0 += acc[mf][nf][0] * a0 + acc[mf][nf][1] * a1;
                s1 += acc[mf][nf][2] * a0 + acc[mf][nf][3] * a1;
                t0 += acc[mf][nf][0] * d0 + acc[mf][nf][1] * d1;
                t1 += acc[mf][nf][2] * d0 + acc[mf][nf][3] * d1;
            }
            ps[mf][0][0] = s0; ps[mf][1][0] = s1;
            ps[mf][0][1] = t0; ps[mf][1][1] = t1;
        }
#pragma unroll
        for (int mf = 0; mf < 2; mf++)
#pragma unroll
            for (int hf = 0; hf < 2; hf++)
#pragma unroll
                for (int q = 0; q < 2; q++) {
                    ps[mf][hf][q] += __shfl_xor_sync(0xFFFFFFFF, ps[mf][hf][q], 1);
                    ps[mf][hf][q] += __shfl_xor_sync(0xFFFFFFFF, ps[mf][hf][q], 2);
                }
        if (tig == 0 && wn == 0) {
#pragma unroll
            for (int mf = 0; mf < 2; mf++)
#pragma unroll
                for (int hf = 0; hf < 2; hf++) {
                    int rl = (wm * 2 + mf) * 16 + hf * 8 + gid;
                    sred[rl * 2 + 0] = ps[mf][hf][0];
                    sred[rl * 2 + 1] = ps[mf][hf][1];
                }
        }
        __syncthreads();
        if (tig == 0 && wn == 1) {
#pragma unroll
            for (int mf = 0; mf < 2; mf++)
#pragma unroll
                for (int hf = 0; hf < 2; hf++) {
                    int rl = (wm * 2 + mf) * 16 + hf * 8 + gid;
                    int row = rowBase + rl;
                    if (row < M) {
                        als[row * H + hd] = ps[mf][hf][0] + sred[rl * 2 + 0];
                        ald[row * H + hd] = ps[mf][hf][1] + sred[rl * 2 + 1];
                    }
                }
        }
    }
}

// ---------------------------------------------------------------------------
// Init: zero degree histogram + pooling accumulators (one launch).
// ---------------------------------------------------------------------------
__global__ void init_kernel(int N)
{
    int i = blockIdx.x * blockDim.x + threadIdx.x;
    if (i < N) g_deg[i] = 0;
    if (i < 64 * 64) g_pool[i] = 0.f;
    if (i < 64) g_cnt[i] = 0.f;
}

__global__ void csr_hist_kernel(const int* __restrict__ ei, int E)
{
    int e = blockIdx.x * blockDim.x + threadIdx.x;
    if (e < E) atomicAdd(&g_deg[ei[E + e]], 1);
}

// Single-block exclusive scan (warp shuffle + cross-warp), N up to MAXN.
__global__ __launch_bounds__(1024) void csr_scan_kernel(int N)
{
    __shared__ int wsum[32];
    __shared__ int carry;
    int tid = threadIdx.x;
    int lane = tid & 31, w = tid >> 5;
    if (tid == 0) { carry = 0; g_rowptr[0] = 0; }
    __syncthreads();
    for (int base = 0; base < N; base += 1024) {
        int i = base + tid;
        int v = (i < N) ? g_deg[i] : 0;
        int x = v;
#pragma unroll
        for (int off = 1; off < 32; off <<= 1) {
            int t = __shfl_up_sync(0xFFFFFFFF, x, off);
            if (lane >= off) x += t;
        }
        if (lane == 31) wsum[w] = x;
        __syncthreads();
        if (w == 0) {
            int s = wsum[lane];
#pragma unroll
            for (int off = 1; off < 32; off <<= 1) {
                int t = __shfl_up_sync(0xFFFFFFFF, s, off);
                if (lane >= off) s += t;
            }
            wsum[lane] = s;
        }
        __syncthreads();
        int incl = x + (w > 0 ? wsum[w - 1] : 0);
        int c = carry;
        if (i < N) {
            g_rowptr[i + 1] = c + incl;
            g_cursor[i] = c + incl - v;
        }
        __syncthreads();
        if (tid == 1023) carry = c + incl;
        __syncthreads();
    }
}

__global__ void csr_fill_kernel(const int* __restrict__ ei, int E)
{
    int e = blockIdx.x * blockDim.x + threadIdx.x;
    if (e >= E) return;
    int s = ei[e], d = ei[E + e];
    int p = atomicAdd(&g_cursor[d], 1);
    g_col[p] = s;
    g_dst[p] = d;
}

// ---------------------------------------------------------------------------
// Edge exp: ex[p,h] = exp(leaky_relu(als[src]+ald[dst])) in CSR order.
// ---------------------------------------------------------------------------
__global__ void edge_ex4_kernel(int E, const float* __restrict__ als,
                                const float* __restrict__ ald)
{
    int p = blockIdx.x * blockDim.x + threadIdx.x;
    if (p >= E) return;
    int s = g_col[p], d = g_dst[p];
    float4 a = *(const float4*)&als[s * 4];
    float4 b = *(const float4*)&ald[d * 4];
    float4 v;
    v.x = a.x + b.x; v.x = (v.x > 0.f) ? v.x : 0.2f * v.x; v.x = __expf(v.x);
    v.y = a.y + b.y; v.y = (v.y > 0.f) ? v.y : 0.2f * v.y; v.y = __expf(v.y);
    v.z = a.z + b.z; v.z = (v.z > 0.f) ? v.z : 0.2f * v.z; v.z = __expf(v.z);
    v.w = a.w + b.w; v.w = (v.w > 0.f) ? v.w : 0.2f * v.w; v.w = __expf(v.w);
    *(float4*)&g_ex[(size_t)p * 4] = v;
}

__global__ void edge_ex1_kernel(int E, const float* __restrict__ als,
                                const float* __restrict__ ald)
{
    int p = blockIdx.x * blockDim.x + threadIdx.x;
    if (p >= E) return;
    float v = als[g_col[p]] + ald[g_dst[p]];
    v = (v > 0.f) ? v : 0.2f * v;
    g_ex[p] = __expf(v);
}

// ---------------------------------------------------------------------------
// Gather (fp16 messages) + softmax-normalize + bias + ELU. TPE = HC/8 threads
// per dst; one uint4 (8 halves) per edge per thread. Output fp16 (HALF_OUT,
// feeds next GEMM) or fp32 (final layer, feeds pooling).
// ---------------------------------------------------------------------------
__device__ __forceinline__ void unpack8(uint4 r, float* v)
{
    float2 p;
    p = __half22float2(*(__half2*)&r.x); v[0] = p.x; v[1] = p.y;
    p = __half22float2(*((__half2*)&r.x + 1)); v[2] = p.x; v[3] = p.y;
    p = __half22float2(*(__half2*)&r.z); v[4] = p.x; v[5] = p.y;
    p = __half22float2(*((__half2*)&r.z + 1)); v[6] = p.x; v[7] = p.y;
}

template <int H, int C, bool HALF_OUT>
__global__ __launch_bounds__(256) void gather_kernel(
    int N, const __half* __restrict__ h,
    const float* __restrict__ als, const float* __restrict__ ald,
    const float* __restrict__ bias, void* __restrict__ outv)
{
    constexpr int HC = H * C;
    constexpr int TPE = HC / 8;
    constexpr int DPB = 256 / TPE;
    int d = blockIdx.x * DPB + threadIdx.x / TPE;
    if (d >= N) return;
    int t = threadIdx.x % TPE;
    int hd = t / (C / 8);

    // self-loop
    float l = als[d * H + hd] + ald[d * H + hd];
    l = (l > 0.f) ? l : 0.2f * l;
    float exs = __expf(l);
    float den = exs;
    float acc[8], v[8];
    uint4 raw = *(const uint4*)(h + (size_t)d * HC + t * 8);
    unpack8(raw, v);
#pragma unroll
    for (int i = 0; i < 8; i++) acc[i] = exs * v[i];

    int p = g_rowptr[d], pend = g_rowptr[d + 1];
    for (; p < pend; p++) {
        int s = g_col[p];
        float ex = g_ex[(size_t)p * H + hd];
        raw = *(const uint4*)(h + (size_t)s * HC + t * 8);
        unpack8(raw, v);
#pragma unroll
        for (int i = 0; i < 8; i++) acc[i] += ex * v[i];
        den += ex;
    }
    float inv = 1.f / (den + 1e-16f);
    float4 bv0 = *(const float4*)(bias + t * 8);
    float4 bv1 = *(const float4*)(bias + t * 8 + 4);
    float bb[8] = {bv0.x, bv0.y, bv0.z, bv0.w, bv1.x, bv1.y, bv1.z, bv1.w};
    float o[8];
#pragma unroll
    for (int i = 0; i < 8; i++) {
        float x = acc[i] * inv + bb[i];
        o[i] = (x > 0.f) ? x : expm1f(x);
    }
    if (HALF_OUT) {
        __half2 ho[4];
#pragma unroll
        for (int i = 0; i < 4; i++) ho[i] = __floats2half2_rn(o[2 * i], o[2 * i + 1]);
        *(uint4*)((__half*)outv + (size_t)d * HC + t * 8) = *(uint4*)ho;
    } else {
        float* op = (float*)outv + (size_t)d * HC + t * 8;
        *(float4*)op = make_float4(o[0], o[1], o[2], o[3]);
        *(float4*)(op + 4) = make_float4(o[4], o[5], o[6], o[7]);
    }
}

// ---------------------------------------------------------------------------
// Pooling (batch is sorted): run-length local accumulate, rare atomic flush.
// ---------------------------------------------------------------------------
__global__ __launch_bounds__(256) void pool_acc_kernel(
    const float* __restrict__ h, const int* __restrict__ batch, int N)
{
    int c = threadIdx.x & 63;
    int lane = threadIdx.x >> 6;
    int n0 = blockIdx.x * 64 + lane * 16;
    float acc = 0.f;
    int curg = -1, cnt = 0;
    for (int k = 0; k < 16; k++) {
        int n = n0 + k;
        if (n >= N) break;
        int g = batch[n];
        if (g != curg) {
            if (curg >= 0) {
                atomicAdd(&g_pool[curg * 64 + c], acc);
                if (c == 0) atomicAdd(&g_cnt[curg], (float)cnt);
            }
            curg = g; acc = 0.f; cnt = 0;
        }
        acc += h[(size_t)n * 64 + c];
        cnt++;
    }
    if (curg >= 0) {
        atomicAdd(&g_pool[curg * 64 + c], acc);
        if (c == 0) atomicAdd(&g_cnt[curg], (float)cnt);
    }
}

__global__ void final_linear_kernel(const float* __restrict__ linW,
                                    const float* __restrict__ linb,
                                    float* __restrict__ out)
{
    int idx = blockIdx.x * blockDim.x + threadIdx.x;
    if (idx >= 64 * 10) return;
    int g = idx / 10, o = idx % 10;
    float inv = 1.f / fmaxf(g_cnt[g], 1.f);
    float s = 0.f;
#pragma unroll 8
    for (int k = 0; k < 64; k++)
        s += g_pool[g * 64 + k] * inv * linW[k * 10 + o];
    out[idx] = s + linb[o];
}

// ---------------------------------------------------------------------------
// Host orchestration. Layer-1 GEMM is user launch #4 (the ncu-profiled one).
// ---------------------------------------------------------------------------
extern "C" void kernel_launch(void* const* d_in, const int* in_sizes, int n_in,
                              void* d_out, int out_size)
{
    const float* x     = (const float*)d_in[0];
    const int*   ei    = (const int*)d_in[1];
    const int*   batch = (const int*)d_in[2];
    const float* W1 = (const float*)d_in[3];   const float* b1 = (const float*)d_in[4];
    const float* as1 = (const float*)d_in[5];  const float* ad1 = (const float*)d_in[6];
    const float* W2 = (const float*)d_in[7];   const float* b2 = (const float*)d_in[8];
    const float* as2 = (const float*)d_in[9];  const float* ad2 = (const float*)d_in[10];
    const float* W3 = (const float*)d_in[11];  const float* b3 = (const float*)d_in[12];
    const float* as3 = (const float*)d_in[13]; const float* ad3 = (const float*)d_in[14];
    const float* linW = (const float*)d_in[15]; const float* linb = (const float*)d_in[16];
    float* out = (float*)d_out;

    int N = in_sizes[0] / 128;
    int E = in_sizes[1] / 2;

    float *als, *ald, *hB3;
    __half *hH, *hG, *xh, *Wh;
    cudaGetSymbolAddress((void**)&hH,  g_hH);
    cudaGetSymbolAddress((void**)&hG,  g_hG);
    cudaGetSymbolAddress((void**)&hB3, g_hB3);
    cudaGetSymbolAddress((void**)&als, g_als);
    cudaGetSymbolAddress((void**)&ald, g_ald);
    cudaGetSymbolAddress((void**)&xh,  g_xh);
    cudaGetSymbolAddress((void**)&Wh,  g_Wh);

    int gemmRows = (N + 127) / 128;

    // 1-3: conversions + init
    convert_x_kernel<<<(N * 32 + 255) / 256, 256>>>(x, xh, N * 32);  // N*128/4
    convert_wT_kernel<<<(114688 + 255) / 256, 256>>>(W1, W2, W3);
    init_kernel<<<(N + 255) / 256, 256>>>(N);

    // 4: layer-1 GEMM (+ fused attn coefs)   <-- profiled launch
    h16_gemm_kernel<<<dim3(4, gemmRows), 256>>>(xh, Wh, hH, N, 256, 128,
                                                as1, ad1, als, ald, 4);
    // 5-7: CSR build
    csr_hist_kernel<<<(E + 255) / 256, 256>>>(ei, E);
    csr_scan_kernel<<<1, 1024>>>(N);
    csr_fill_kernel<<<(E + 255) / 256, 256>>>(ei, E);

    // Layer 1 edge phase (fp16 out: feeds GEMM2)
    edge_ex4_kernel<<<(E + 255) / 256, 256>>>(E, als, ald);
    gather_kernel<4, 64, true><<<(N + 7) / 8, 256>>>(N, hH, als, ald, b1, hG);

    // Layer 2
    h16_gemm_kernel<<<dim3(4, gemmRows), 256>>>(hG, Wh + 32768, hH, N, 256, 256,
                                                as2, ad2, als, ald, 4);
    edge_ex4_kernel<<<(E + 255) / 256, 256>>>(E, als, ald);
    gather_kernel<4, 64, true><<<(N + 7) / 8, 256>>>(N, hH, als, ald, b2, hG);

    // Layer 3 (fp32 out: feeds pooling)
    h16_gemm_kernel<<<dim3(1, gemmRows), 256>>>(hG, Wh + 98304, hH, N, 64, 256,
                                                as3, ad3, als, ald, 1);
    edge_ex1_kernel<<<(E + 255) / 256, 256>>>(E, als, ald);
    gather_kernel<1, 64, false><<<(N + 31) / 32, 256>>>(N, hH, als, ald, b3, hB3);

    // Pool + final linear
    pool_acc_kernel<<<(N + 63) / 64, 256>>>(hB3, batch, N);
    final_linear_kernel<<<3, 256>>>(linW, linb, out);
}